// round 4
// baseline (speedup 1.0000x reference)
#include <cuda_runtime.h>
#include <cstdint>

#define N_NODES 20000
#define N_REL 32
#define HID 128
#define EMBD 16
#define N_EDGES 600000
#define NSEG (N_NODES * N_REL)   // 640000
#define SCAN_BLOCKS (NSEG / 1024) // 625 exactly

// ---------------- scratch (device globals, 16B-aligned; ~25 MB total) ----------------
__device__ __align__(16) int   g_scnt[NSEG];          // per-(dst,rel) segment edge counts
__device__ __align__(16) int   g_tmp[NSEG];           // per-block inclusive scan values
__device__ __align__(16) int   g_rowptr[NSEG + 1];    // segment CSR row pointers
__device__ __align__(16) int   g_cursor[NSEG];        // bucket-fill cursors
__device__ __align__(16) float g_inv[NSEG];           // 1/count per segment (0 if empty)
__device__ __align__(16) int   g_esrc[N_EDGES];       // src index per edge, bucketed by segment
__device__ __align__(16) float g_h1[N_NODES * HID];   // layer-1 activations (post-ReLU), 10.24 MB
__device__ __align__(16) int   g_bsum[SCAN_BLOCKS];
__device__ __align__(16) int   g_bexcl[SCAN_BLOCKS];
__device__ int g_ei64;  // 1 if edge_index is int64, 0 if int32
__device__ int g_et64;  // 1 if edge_type  is int64, 0 if int32

// index decode helpers (branch is uniform; flag cached in L2)
__device__ __forceinline__ int load_idx(const void* p, long long i, int is64) {
    return is64 ? (int)((const long long*)p)[i] : ((const int*)p)[i];
}

// ---------------- dtype detection ----------------
// If data is int64 with values < 2^31, every odd 32-bit word is 0.
// For int32 index data, odd words are random indices -> P(all zero) ~ 0.
__global__ void k_detect(const int* __restrict__ ei, const int* __restrict__ et) {
    if (blockIdx.x == 0 && threadIdx.x == 0) {
        int a = 1, b = 1;
        for (int i = 0; i < 64; i++) {
            if (ei[2 * i + 1] != 0) { a = 0; break; }
        }
        for (int i = 0; i < 64; i++) {
            if (et[2 * i + 1] != 0) { b = 0; break; }
        }
        g_ei64 = a;
        g_et64 = b;
    }
}

// ---------------- preprocessing ----------------
__global__ void k_init() {
    int i0 = blockIdx.x * blockDim.x + threadIdx.x;
    int stride = gridDim.x * blockDim.x;
    for (int i = i0; i < NSEG; i += stride) g_scnt[i] = 0;
}

__global__ void k_count(const void* __restrict__ ei, const void* __restrict__ et) {
    int i0 = blockIdx.x * blockDim.x + threadIdx.x;
    int stride = gridDim.x * blockDim.x;
    int e64 = g_ei64, t64 = g_et64;
    for (int e = i0; e < N_EDGES; e += stride) {
        int dst = load_idx(ei, (long long)N_EDGES + e, e64);
        int r = load_idx(et, e, t64);
        if ((unsigned)dst >= N_NODES || (unsigned)r >= N_REL) continue;  // safety
        atomicAdd(&g_scnt[dst * N_REL + r], 1);
    }
}

// per-1024-block inclusive scan; also derives inverse counts
__global__ void k_scan1() {
    __shared__ int sdata[1024];
    int tid = threadIdx.x;
    int i = blockIdx.x * 1024 + tid;
    int v = g_scnt[i];
    g_inv[i] = (v > 0) ? (1.0f / (float)v) : 0.0f;
    sdata[tid] = v;
    __syncthreads();
    for (int off = 1; off < 1024; off <<= 1) {
        int tmp = (tid >= off) ? sdata[tid - off] : 0;
        __syncthreads();
        sdata[tid] += tmp;
        __syncthreads();
    }
    g_tmp[i] = sdata[tid];
    if (tid == 1023) g_bsum[blockIdx.x] = sdata[1023];
}

// scan the 625 block sums (single block)
__global__ void k_scan2() {
    __shared__ int sdata[1024];
    int tid = threadIdx.x;
    int v = (tid < SCAN_BLOCKS) ? g_bsum[tid] : 0;
    sdata[tid] = v;
    __syncthreads();
    for (int off = 1; off < 1024; off <<= 1) {
        int tmp = (tid >= off) ? sdata[tid - off] : 0;
        __syncthreads();
        sdata[tid] += tmp;
        __syncthreads();
    }
    if (tid < SCAN_BLOCKS) g_bexcl[tid] = sdata[tid] - v;  // exclusive
}

// combine -> rowptr (inclusive ends) and cursor (exclusive starts)
__global__ void k_scan3() {
    int i0 = blockIdx.x * blockDim.x + threadIdx.x;
    int stride = gridDim.x * blockDim.x;
    for (int i = i0; i < NSEG; i += stride) {
        int val = g_bexcl[i >> 10] + g_tmp[i];
        g_rowptr[i + 1] = val;
        g_cursor[i] = val - g_scnt[i];
    }
    if (i0 == 0) g_rowptr[0] = 0;
}

__global__ void k_bucket(const void* __restrict__ ei, const void* __restrict__ et) {
    int i0 = blockIdx.x * blockDim.x + threadIdx.x;
    int stride = gridDim.x * blockDim.x;
    int e64 = g_ei64, t64 = g_et64;
    for (int e = i0; e < N_EDGES; e += stride) {
        int src = load_idx(ei, e, e64);
        int dst = load_idx(ei, (long long)N_EDGES + e, e64);
        int r = load_idx(et, e, t64);
        if ((unsigned)src >= N_NODES || (unsigned)dst >= N_NODES || (unsigned)r >= N_REL) continue;
        int idx = atomicAdd(&g_cursor[dst * N_REL + r], 1);
        g_esrc[idx] = src;
    }
}

// ---------------- layer 1: h1 = relu( A1[20000x512] @ W1flat[512x128] + emb @ root1 + b1 ) ----
// A1[dst][r*16+f] = inv(dst,r) * sum_{e in seg(dst,r)} x[src][f], gathered on the fly.
// grid 625, block 128; 32 dst rows x 128 cols per block.
__global__ void __launch_bounds__(128) k_l1(const float* __restrict__ emb,
                                            const float* __restrict__ W1,
                                            const float* __restrict__ root1,
                                            const float* __restrict__ b1) {
    __shared__ float As[32][36];   // [dst][k-in-chunk]
    __shared__ float Bs[32][132];  // [k-in-chunk][col]
    int n0 = blockIdx.x * 32;
    int t = threadIdx.x;
    int d = t >> 2, sub = t & 3;            // gather roles: 4 threads per dst
    int brow = t >> 2, bc0 = (t & 3) * 32;  // B-load roles
    int rowT = t >> 4, colT = t & 15;       // compute roles
    int d0 = rowT * 4, col0 = colT * 8;

    float acc[4][8];
#pragma unroll
    for (int i = 0; i < 4; i++)
#pragma unroll
        for (int j = 0; j < 8; j++) acc[i][j] = 0.f;

    // 16 chunks of K=32 (two relations x 16 features each)
    for (int kc = 0; kc < 16; ++kc) {
        __syncthreads();
        // B tile: W1flat rows [kc*32, kc*32+32)
        {
            const float* Bsrc = &W1[(size_t)(kc * 32 + brow) * HID + bc0];
#pragma unroll
            for (int j = 0; j < 8; j++)
                *(float4*)&Bs[brow][bc0 + j * 4] = *(const float4*)(Bsrc + j * 4);
        }
        // A gather: thread covers (rel = 2kc + (sub>>1), f0 = (sub&1)*8, 8 features)
        {
            int rel = kc * 2 + (sub >> 1);
            int f0 = (sub & 1) * 8;
            int seg = (n0 + d) * N_REL + rel;
            int s = g_rowptr[seg], e = g_rowptr[seg + 1];
            float a[8];
#pragma unroll
            for (int i = 0; i < 8; i++) a[i] = 0.f;
            for (int j = s; j < e; ++j) {
                int src = g_esrc[j];
                const float* xp = &emb[src * EMBD + f0];
                float4 v0 = *(const float4*)xp;
                float4 v1 = *(const float4*)(xp + 4);
                a[0] += v0.x; a[1] += v0.y; a[2] += v0.z; a[3] += v0.w;
                a[4] += v1.x; a[5] += v1.y; a[6] += v1.z; a[7] += v1.w;
            }
            float inv = g_inv[seg];
            *(float4*)&As[d][sub * 8]     = make_float4(a[0] * inv, a[1] * inv, a[2] * inv, a[3] * inv);
            *(float4*)&As[d][sub * 8 + 4] = make_float4(a[4] * inv, a[5] * inv, a[6] * inv, a[7] * inv);
        }
        __syncthreads();
#pragma unroll
        for (int k = 0; k < 32; ++k) {
            float4 b0 = *(const float4*)&Bs[k][col0];
            float4 b1v = *(const float4*)&Bs[k][col0 + 4];
            float bv[8] = {b0.x, b0.y, b0.z, b0.w, b1v.x, b1v.y, b1v.z, b1v.w};
#pragma unroll
            for (int i = 0; i < 4; ++i) {
                float av = As[d0 + i][k];
#pragma unroll
                for (int j = 0; j < 8; ++j) acc[i][j] += av * bv[j];
            }
        }
    }

    // root chunk: K = 16, A = emb rows, B = root1
    __syncthreads();
    {
        int f0 = (t & 3) * 4;  // 4 floats per thread
        float4 v = *(const float4*)&emb[(n0 + d) * EMBD + f0];
        *(float4*)&As[d][f0] = v;
        int rb = t >> 3, rc0 = (t & 7) * 16;
#pragma unroll
        for (int j = 0; j < 4; j++)
            *(float4*)&Bs[rb][rc0 + j * 4] = *(const float4*)&root1[rb * HID + rc0 + j * 4];
    }
    __syncthreads();
#pragma unroll
    for (int k = 0; k < 16; ++k) {
        float4 b0 = *(const float4*)&Bs[k][col0];
        float4 b1v = *(const float4*)&Bs[k][col0 + 4];
        float bv[8] = {b0.x, b0.y, b0.z, b0.w, b1v.x, b1v.y, b1v.z, b1v.w};
#pragma unroll
        for (int i = 0; i < 4; ++i) {
            float av = As[d0 + i][k];
#pragma unroll
            for (int j = 0; j < 8; ++j) acc[i][j] += av * bv[j];
        }
    }

    // epilogue: + b1, relu -> g_h1
    float4 bb0 = *(const float4*)&b1[col0];
    float4 bb1 = *(const float4*)&b1[col0 + 4];
    float bb[8] = {bb0.x, bb0.y, bb0.z, bb0.w, bb1.x, bb1.y, bb1.z, bb1.w};
#pragma unroll
    for (int i = 0; i < 4; ++i) {
        int n = n0 + d0 + i;
        float o[8];
#pragma unroll
        for (int j = 0; j < 8; ++j) o[j] = fmaxf(acc[i][j] + bb[j], 0.f);
        *(float4*)&g_h1[n * HID + col0]     = make_float4(o[0], o[1], o[2], o[3]);
        *(float4*)&g_h1[n * HID + col0 + 4] = make_float4(o[4], o[5], o[6], o[7]);
    }
}

// ---------------- layer 2: out = A2[20000x4096] @ W2flat + h1 @ root2 + b2 ----------------
// A2[dst][r*128+h] = inv(dst,r) * sum_{e in seg(dst,r)} h1[src][h], gathered on the fly.
// grid 625, block 128; kc 0..127 = relation chunks, kc 128..131 = root chunks.
__global__ void __launch_bounds__(128) k_l2(const float* __restrict__ W2,
                                            const float* __restrict__ root2,
                                            const float* __restrict__ b2,
                                            float* __restrict__ out) {
    __shared__ float As[32][36];
    __shared__ float Bs[32][132];
    int n0 = blockIdx.x * 32;
    int t = threadIdx.x;
    int d = t >> 2, sub = t & 3;
    int brow = t >> 2, bc0 = (t & 3) * 32;
    int rowT = t >> 4, colT = t & 15;
    int d0 = rowT * 4, col0 = colT * 8;

    float acc[4][8];
#pragma unroll
    for (int i = 0; i < 4; i++)
#pragma unroll
        for (int j = 0; j < 8; j++) acc[i][j] = 0.f;

    for (int kc = 0; kc < 132; ++kc) {
        __syncthreads();
        // B tile
        {
            const float* Bsrc = (kc < 128)
                ? &W2[(size_t)(kc * 32 + brow) * HID + bc0]
                : &root2[(size_t)((kc - 128) * 32 + brow) * HID + bc0];
#pragma unroll
            for (int j = 0; j < 8; j++)
                *(float4*)&Bs[brow][bc0 + j * 4] = *(const float4*)(Bsrc + j * 4);
        }
        // A gather
        {
            float a[8];
            if (kc < 128) {
                int rel = kc >> 2;
                int h = (kc & 3) * 32 + sub * 8;
                int seg = (n0 + d) * N_REL + rel;
                int s = g_rowptr[seg], e = g_rowptr[seg + 1];
#pragma unroll
                for (int i = 0; i < 8; i++) a[i] = 0.f;
                for (int j = s; j < e; ++j) {
                    int src = g_esrc[j];
                    const float* hp = &g_h1[src * HID + h];
                    float4 v0 = *(const float4*)hp;
                    float4 v1 = *(const float4*)(hp + 4);
                    a[0] += v0.x; a[1] += v0.y; a[2] += v0.z; a[3] += v0.w;
                    a[4] += v1.x; a[5] += v1.y; a[6] += v1.z; a[7] += v1.w;
                }
                float inv = g_inv[seg];
#pragma unroll
                for (int i = 0; i < 8; i++) a[i] *= inv;
            } else {
                int h = (kc - 128) * 32 + sub * 8;
                const float* hp = &g_h1[(n0 + d) * HID + h];
                float4 v0 = *(const float4*)hp;
                float4 v1 = *(const float4*)(hp + 4);
                a[0] = v0.x; a[1] = v0.y; a[2] = v0.z; a[3] = v0.w;
                a[4] = v1.x; a[5] = v1.y; a[6] = v1.z; a[7] = v1.w;
            }
            *(float4*)&As[d][sub * 8]     = make_float4(a[0], a[1], a[2], a[3]);
            *(float4*)&As[d][sub * 8 + 4] = make_float4(a[4], a[5], a[6], a[7]);
        }
        __syncthreads();
#pragma unroll
        for (int k = 0; k < 32; ++k) {
            float4 b0 = *(const float4*)&Bs[k][col0];
            float4 b1v = *(const float4*)&Bs[k][col0 + 4];
            float bv[8] = {b0.x, b0.y, b0.z, b0.w, b1v.x, b1v.y, b1v.z, b1v.w};
#pragma unroll
            for (int i = 0; i < 4; ++i) {
                float av = As[d0 + i][k];
#pragma unroll
                for (int j = 0; j < 8; ++j) acc[i][j] += av * bv[j];
            }
        }
    }

    // epilogue: + b2 -> out
    float4 bb0 = *(const float4*)&b2[col0];
    float4 bb1 = *(const float4*)&b2[col0 + 4];
    float bb[8] = {bb0.x, bb0.y, bb0.z, bb0.w, bb1.x, bb1.y, bb1.z, bb1.w};
#pragma unroll
    for (int i = 0; i < 4; ++i) {
        int n = n0 + d0 + i;
        *(float4*)&out[(size_t)n * HID + col0] =
            make_float4(acc[i][0] + bb[0], acc[i][1] + bb[1], acc[i][2] + bb[2], acc[i][3] + bb[3]);
        *(float4*)&out[(size_t)n * HID + col0 + 4] =
            make_float4(acc[i][4] + bb[4], acc[i][5] + bb[5], acc[i][6] + bb[6], acc[i][7] + bb[7]);
    }
}

// ---------------- launch ----------------
extern "C" void kernel_launch(void* const* d_in, const int* in_sizes, int n_in,
                              void* d_out, int out_size) {
    const void* edge_index = d_in[0];
    const void* edge_type = d_in[1];
    const float* node_emb = (const float*)d_in[2];
    const float* W1 = (const float*)d_in[3];
    const float* root1 = (const float*)d_in[4];
    const float* b1 = (const float*)d_in[5];
    const float* W2 = (const float*)d_in[6];
    const float* root2 = (const float*)d_in[7];
    const float* b2 = (const float*)d_in[8];
    float* out = (float*)d_out;

    // dtype detection (int32 vs int64 index arrays)
    k_detect<<<1, 32>>>((const int*)edge_index, (const int*)edge_type);

    // segment-CSR preprocessing (shared by both layers)
    k_init<<<640, 1024>>>();
    k_count<<<1172, 256>>>(edge_index, edge_type);
    k_scan1<<<SCAN_BLOCKS, 1024>>>();
    k_scan2<<<1, 1024>>>();
    k_scan3<<<640, 1024>>>();
    k_bucket<<<1172, 256>>>(edge_index, edge_type);

    // layer 1: fused gather-GEMM -> g_h1
    k_l1<<<625, 128>>>(node_emb, W1, root1, b1);
    // layer 2: fused gather-GEMM -> out
    k_l2<<<625, 128>>>(W2, root2, b2, out);
}

// round 5
// speedup vs baseline: 1.7091x; 1.7091x over previous
#include <cuda_runtime.h>
#include <cstdint>

#define N_NODES 20000
#define N_REL 32
#define HID 128
#define EMBD 16
#define N_EDGES 600000
#define NSEG (N_NODES * N_REL)    // 640000
#define SCAN_BLOCKS (NSEG / 1024) // 625 exactly

// ---------------- scratch (device globals, 16B-aligned; ~25 MB) ----------------
__device__ __align__(16) int   g_scnt[NSEG];
__device__ __align__(16) int   g_tmp[NSEG];
__device__ __align__(16) int   g_rowptr[NSEG + 1];
__device__ __align__(16) int   g_cursor[NSEG];
__device__ __align__(16) float g_inv[NSEG];
__device__ __align__(16) int   g_esrc[N_EDGES];     // (rel<<16)|src per edge, bucketed by segment
__device__ __align__(16) float g_h1[N_NODES * HID];
__device__ __align__(16) int   g_bsum[SCAN_BLOCKS];
__device__ __align__(16) int   g_bexcl[SCAN_BLOCKS];
__device__ int g_ei64;
__device__ int g_et64;

__device__ __forceinline__ int load_idx(const void* p, long long i, int is64) {
    return is64 ? (int)((const long long*)p)[i] : ((const int*)p)[i];
}

// ---------------- dtype detection (int32 vs int64 index arrays) ----------------
__global__ void k_detect(const int* __restrict__ ei, const int* __restrict__ et) {
    if (blockIdx.x == 0 && threadIdx.x == 0) {
        int a = 1, b = 1;
        for (int i = 0; i < 64; i++) if (ei[2 * i + 1] != 0) { a = 0; break; }
        for (int i = 0; i < 64; i++) if (et[2 * i + 1] != 0) { b = 0; break; }
        g_ei64 = a;
        g_et64 = b;
    }
}

// ---------------- preprocessing ----------------
__global__ void k_init() {
    int i0 = blockIdx.x * blockDim.x + threadIdx.x;
    int stride = gridDim.x * blockDim.x;
    for (int i = i0; i < NSEG; i += stride) g_scnt[i] = 0;
}

__global__ void k_count(const void* __restrict__ ei, const void* __restrict__ et) {
    int i0 = blockIdx.x * blockDim.x + threadIdx.x;
    int stride = gridDim.x * blockDim.x;
    int e64 = g_ei64, t64 = g_et64;
    for (int e = i0; e < N_EDGES; e += stride) {
        int dst = load_idx(ei, (long long)N_EDGES + e, e64);
        int r = load_idx(et, e, t64);
        if ((unsigned)dst >= N_NODES || (unsigned)r >= N_REL) continue;
        atomicAdd(&g_scnt[dst * N_REL + r], 1);
    }
}

__global__ void k_scan1() {
    __shared__ int sdata[1024];
    int tid = threadIdx.x;
    int i = blockIdx.x * 1024 + tid;
    int v = g_scnt[i];
    g_inv[i] = (v > 0) ? (1.0f / (float)v) : 0.0f;
    sdata[tid] = v;
    __syncthreads();
    for (int off = 1; off < 1024; off <<= 1) {
        int tmp = (tid >= off) ? sdata[tid - off] : 0;
        __syncthreads();
        sdata[tid] += tmp;
        __syncthreads();
    }
    g_tmp[i] = sdata[tid];
    if (tid == 1023) g_bsum[blockIdx.x] = sdata[1023];
}

__global__ void k_scan2() {
    __shared__ int sdata[1024];
    int tid = threadIdx.x;
    int v = (tid < SCAN_BLOCKS) ? g_bsum[tid] : 0;
    sdata[tid] = v;
    __syncthreads();
    for (int off = 1; off < 1024; off <<= 1) {
        int tmp = (tid >= off) ? sdata[tid - off] : 0;
        __syncthreads();
        sdata[tid] += tmp;
        __syncthreads();
    }
    if (tid < SCAN_BLOCKS) g_bexcl[tid] = sdata[tid] - v;
}

__global__ void k_scan3() {
    int i0 = blockIdx.x * blockDim.x + threadIdx.x;
    int stride = gridDim.x * blockDim.x;
    for (int i = i0; i < NSEG; i += stride) {
        int val = g_bexcl[i >> 10] + g_tmp[i];
        g_rowptr[i + 1] = val;
        g_cursor[i] = val - g_scnt[i];
    }
    if (i0 == 0) g_rowptr[0] = 0;
}

__global__ void k_bucket(const void* __restrict__ ei, const void* __restrict__ et) {
    int i0 = blockIdx.x * blockDim.x + threadIdx.x;
    int stride = gridDim.x * blockDim.x;
    int e64 = g_ei64, t64 = g_et64;
    for (int e = i0; e < N_EDGES; e += stride) {
        int src = load_idx(ei, e, e64);
        int dst = load_idx(ei, (long long)N_EDGES + e, e64);
        int r = load_idx(et, e, t64);
        if ((unsigned)src >= N_NODES || (unsigned)dst >= N_NODES || (unsigned)r >= N_REL) continue;
        int idx = atomicAdd(&g_cursor[dst * N_REL + r], 1);
        g_esrc[idx] = (r << 16) | src;
    }
}

// ==================== layer 1 ====================
// h1 = relu( A1[20000x512] @ W1flat[512x128] + emb @ root1 + b1 )
// Block: 256 threads, 32 dst rows. Full A-panel [32 x 528] gathered ONCE into smem,
// then 17 streaming B chunks of K<=32. acc 4x4 per thread.
#define L1_AS 548                   // A row stride (528 data + pad, 16B-mult)
#define L1_SMEM ((32 * L1_AS + 32 * 132) * 4)

__global__ void __launch_bounds__(256) k_l1(const float* __restrict__ emb,
                                            const float* __restrict__ W1,
                                            const float* __restrict__ root1,
                                            const float* __restrict__ b1) {
    extern __shared__ float sm[];
    float* As = sm;                 // [32][548]
    float* Bs = sm + 32 * L1_AS;    // [32][132]
    int n0 = blockIdx.x * 32;
    int t = threadIdx.x;

    // ---- gather roles: d = dst-in-tile, handles features f0, f0+1 over all rels ----
    int d = t >> 3, sub = t & 7, f0 = sub * 2;

    // zero the rel part of A (cols 0..511)
    float4 z4 = make_float4(0.f, 0.f, 0.f, 0.f);
#pragma unroll
    for (int q = 0; q < 16; ++q)
        *(float4*)&As[d * L1_AS + sub * 64 + q * 4] = z4;
    __syncthreads();

    // walk full contiguous edge range of this dst (all 32 rel segments)
    int base = (n0 + d) * N_REL;
    int s = g_rowptr[base], e = g_rowptr[base + N_REL];
    for (int j = s; j < e; ++j) {
        int p = g_esrc[j];
        int src = p & 0xFFFF, rel = p >> 16;
        float2 v = *(const float2*)&emb[src * EMBD + f0];
        As[d * L1_AS + rel * 16 + f0]     += v.x;
        As[d * L1_AS + rel * 16 + f0 + 1] += v.y;
    }
    // scale by per-(dst,rel) inverse counts
#pragma unroll 8
    for (int rel = 0; rel < N_REL; ++rel) {
        float iv = g_inv[base + rel];
        As[d * L1_AS + rel * 16 + f0]     *= iv;
        As[d * L1_AS + rel * 16 + f0 + 1] *= iv;
    }
    // root chunk cols 512..527 = emb row (unscaled)
    {
        float2 rv = *(const float2*)&emb[(n0 + d) * EMBD + f0];
        As[d * L1_AS + 512 + f0]     = rv.x;
        As[d * L1_AS + 512 + f0 + 1] = rv.y;
    }

    // ---- compute roles ----
    int d0 = (t >> 5) * 4;          // 8 row-groups of 4 dsts (uniform in warp -> A broadcast)
    int col0 = (t & 31) * 4;        // 32 col-threads x 4 cols
    float acc[4][4];
#pragma unroll
    for (int i = 0; i < 4; i++)
#pragma unroll
        for (int j = 0; j < 4; j++) acc[i][j] = 0.f;

    for (int kc = 0; kc <= 16; ++kc) {
        int krows = (kc < 16) ? 32 : 16;
        const float* Bsrc = (kc < 16) ? (W1 + (size_t)(kc * 32) * HID) : root1;
        __syncthreads();  // previous compute done before Bs overwrite (covers gather on kc=0)
        {
            int row = t >> 3, c0f = (t & 7) * 16;
            if (row < krows) {
#pragma unroll
                for (int q = 0; q < 4; ++q)
                    *(float4*)&Bs[row * 132 + c0f + q * 4] =
                        *(const float4*)&Bsrc[(size_t)row * HID + c0f + q * 4];
            }
        }
        __syncthreads();
        int kbase = kc * 32;
        int nk4 = krows >> 2;
#pragma unroll 4
        for (int k4 = 0; k4 < nk4; ++k4) {
            int kb = kbase + k4 * 4;
            float4 a0 = *(const float4*)&As[(d0 + 0) * L1_AS + kb];
            float4 a1 = *(const float4*)&As[(d0 + 1) * L1_AS + kb];
            float4 a2 = *(const float4*)&As[(d0 + 2) * L1_AS + kb];
            float4 a3 = *(const float4*)&As[(d0 + 3) * L1_AS + kb];
            int kk = k4 * 4;
            float4 b0 = *(const float4*)&Bs[(kk + 0) * 132 + col0];
            float4 b1v = *(const float4*)&Bs[(kk + 1) * 132 + col0];
            float4 b2v = *(const float4*)&Bs[(kk + 2) * 132 + col0];
            float4 b3v = *(const float4*)&Bs[(kk + 3) * 132 + col0];
#define L1ROW(i, av)                                                                   \
            acc[i][0] += av.x * b0.x;  acc[i][1] += av.x * b0.y;                       \
            acc[i][2] += av.x * b0.z;  acc[i][3] += av.x * b0.w;                       \
            acc[i][0] += av.y * b1v.x; acc[i][1] += av.y * b1v.y;                      \
            acc[i][2] += av.y * b1v.z; acc[i][3] += av.y * b1v.w;                      \
            acc[i][0] += av.z * b2v.x; acc[i][1] += av.z * b2v.y;                      \
            acc[i][2] += av.z * b2v.z; acc[i][3] += av.z * b2v.w;                      \
            acc[i][0] += av.w * b3v.x; acc[i][1] += av.w * b3v.y;                      \
            acc[i][2] += av.w * b3v.z; acc[i][3] += av.w * b3v.w;
            L1ROW(0, a0) L1ROW(1, a1) L1ROW(2, a2) L1ROW(3, a3)
#undef L1ROW
        }
    }

    // epilogue: + b1, relu -> g_h1
    float4 bb = *(const float4*)&b1[col0];
#pragma unroll
    for (int i = 0; i < 4; ++i) {
        int n = n0 + d0 + i;
        float4 v = make_float4(fmaxf(acc[i][0] + bb.x, 0.f), fmaxf(acc[i][1] + bb.y, 0.f),
                               fmaxf(acc[i][2] + bb.z, 0.f), fmaxf(acc[i][3] + bb.w, 0.f));
        *(float4*)&g_h1[(size_t)n * HID + col0] = v;
    }
}

// ==================== layer 2 ====================
// out = A2[20000x4224] @ [W2flat; root2] + b2, A-slices gathered per relation.
// Block: 256 threads, 32 dst rows. Per rel: gather [32x128] A-slice + load [128x128] B,
// one barrier pair, 128 k-iters. acc 4x4. 2 blocks/SM co-residency hides gather latency.
#define L2_SMEM ((32 * 136 + 128 * 132) * 4)

__global__ void __launch_bounds__(256) k_l2(const float* __restrict__ W2,
                                            const float* __restrict__ root2,
                                            const float* __restrict__ b2,
                                            float* __restrict__ out) {
    extern __shared__ float sm[];
    float* As = sm;                 // [32][136]
    float* Bs = sm + 32 * 136;      // [128][132]
    int n0 = blockIdx.x * 32;
    int t = threadIdx.x;

    int d = t >> 3, sub = t & 7;    // gather roles: 8 threads/dst, 16 cols each
    int d0 = (t >> 5) * 4;          // compute roles (A broadcast within warp)
    int col0 = (t & 31) * 4;

    float acc[4][4];
#pragma unroll
    for (int i = 0; i < 4; i++)
#pragma unroll
        for (int j = 0; j < 4; j++) acc[i][j] = 0.f;

    for (int rel = 0; rel <= N_REL; ++rel) {
        __syncthreads();  // previous compute done before As/Bs overwrite
        // ---- B tile: 128 x 128 ----
        {
            const float* Bsrc = (rel < N_REL) ? (W2 + (size_t)rel * HID * HID) : root2;
            int c4 = (t & 31) * 4, r0 = t >> 5;
#pragma unroll
            for (int i = 0; i < 16; ++i) {
                int row = r0 + i * 8;
                *(float4*)&Bs[row * 132 + c4] = *(const float4*)&Bsrc[(size_t)row * HID + c4];
            }
        }
        // ---- A slice: gather 32 x 128 ----
        {
            float4 a0, a1, a2, a3;
            if (rel < N_REL) {
                int seg = (n0 + d) * N_REL + rel;
                int s = g_rowptr[seg], e = g_rowptr[seg + 1];
                a0 = a1 = a2 = a3 = make_float4(0.f, 0.f, 0.f, 0.f);
                for (int j = s; j < e; ++j) {
                    int src = g_esrc[j] & 0xFFFF;
                    const float* hp = &g_h1[(size_t)src * HID + sub * 16];
                    float4 v0 = *(const float4*)(hp + 0);
                    float4 v1 = *(const float4*)(hp + 4);
                    float4 v2 = *(const float4*)(hp + 8);
                    float4 v3 = *(const float4*)(hp + 12);
                    a0.x += v0.x; a0.y += v0.y; a0.z += v0.z; a0.w += v0.w;
                    a1.x += v1.x; a1.y += v1.y; a1.z += v1.z; a1.w += v1.w;
                    a2.x += v2.x; a2.y += v2.y; a2.z += v2.z; a2.w += v2.w;
                    a3.x += v3.x; a3.y += v3.y; a3.z += v3.z; a3.w += v3.w;
                }
                float iv = g_inv[seg];
                a0.x *= iv; a0.y *= iv; a0.z *= iv; a0.w *= iv;
                a1.x *= iv; a1.y *= iv; a1.z *= iv; a1.w *= iv;
                a2.x *= iv; a2.y *= iv; a2.z *= iv; a2.w *= iv;
                a3.x *= iv; a3.y *= iv; a3.z *= iv; a3.w *= iv;
            } else {  // root term: A = h1 row itself
                const float* hp = &g_h1[(size_t)(n0 + d) * HID + sub * 16];
                a0 = *(const float4*)(hp + 0);
                a1 = *(const float4*)(hp + 4);
                a2 = *(const float4*)(hp + 8);
                a3 = *(const float4*)(hp + 12);
            }
            float* ap = &As[d * 136 + sub * 16];
            *(float4*)(ap + 0) = a0;
            *(float4*)(ap + 4) = a1;
            *(float4*)(ap + 8) = a2;
            *(float4*)(ap + 12) = a3;
        }
        __syncthreads();
        // ---- GEMM: 128 k-iters ----
#pragma unroll 4
        for (int k4 = 0; k4 < 32; ++k4) {
            int kb = k4 * 4;
            float4 a0 = *(const float4*)&As[(d0 + 0) * 136 + kb];
            float4 a1 = *(const float4*)&As[(d0 + 1) * 136 + kb];
            float4 a2 = *(const float4*)&As[(d0 + 2) * 136 + kb];
            float4 a3 = *(const float4*)&As[(d0 + 3) * 136 + kb];
            float4 b0 = *(const float4*)&Bs[(kb + 0) * 132 + col0];
            float4 b1v = *(const float4*)&Bs[(kb + 1) * 132 + col0];
            float4 b2v = *(const float4*)&Bs[(kb + 2) * 132 + col0];
            float4 b3v = *(const float4*)&Bs[(kb + 3) * 132 + col0];
#define L2ROW(i, av)                                                                   \
            acc[i][0] += av.x * b0.x;  acc[i][1] += av.x * b0.y;                       \
            acc[i][2] += av.x * b0.z;  acc[i][3] += av.x * b0.w;                       \
            acc[i][0] += av.y * b1v.x; acc[i][1] += av.y * b1v.y;                      \
            acc[i][2] += av.y * b1v.z; acc[i][3] += av.y * b1v.w;                      \
            acc[i][0] += av.z * b2v.x; acc[i][1] += av.z * b2v.y;                      \
            acc[i][2] += av.z * b2v.z; acc[i][3] += av.z * b2v.w;                      \
            acc[i][0] += av.w * b3v.x; acc[i][1] += av.w * b3v.y;                      \
            acc[i][2] += av.w * b3v.z; acc[i][3] += av.w * b3v.w;
            L2ROW(0, a0) L2ROW(1, a1) L2ROW(2, a2) L2ROW(3, a3)
#undef L2ROW
        }
    }

    // epilogue: + b2 -> out
    float4 bb = *(const float4*)&b2[col0];
#pragma unroll
    for (int i = 0; i < 4; ++i) {
        int n = n0 + d0 + i;
        *(float4*)&out[(size_t)n * HID + col0] =
            make_float4(acc[i][0] + bb.x, acc[i][1] + bb.y, acc[i][2] + bb.z, acc[i][3] + bb.w);
    }
}

// ---------------- launch ----------------
extern "C" void kernel_launch(void* const* d_in, const int* in_sizes, int n_in,
                              void* d_out, int out_size) {
    const void* edge_index = d_in[0];
    const void* edge_type = d_in[1];
    const float* node_emb = (const float*)d_in[2];
    const float* W1 = (const float*)d_in[3];
    const float* root1 = (const float*)d_in[4];
    const float* b1 = (const float*)d_in[5];
    const float* W2 = (const float*)d_in[6];
    const float* root2 = (const float*)d_in[7];
    const float* b2 = (const float*)d_in[8];
    float* out = (float*)d_out;

    cudaFuncSetAttribute(k_l1, cudaFuncAttributeMaxDynamicSharedMemorySize, L1_SMEM);
    cudaFuncSetAttribute(k_l2, cudaFuncAttributeMaxDynamicSharedMemorySize, L2_SMEM);

    k_detect<<<1, 32>>>((const int*)edge_index, (const int*)edge_type);

    k_init<<<640, 1024>>>();
    k_count<<<1172, 256>>>(edge_index, edge_type);
    k_scan1<<<SCAN_BLOCKS, 1024>>>();
    k_scan2<<<1, 1024>>>();
    k_scan3<<<640, 1024>>>();
    k_bucket<<<1172, 256>>>(edge_index, edge_type);

    k_l1<<<625, 256, L1_SMEM>>>(node_emb, W1, root1, b1);
    k_l2<<<625, 256, L2_SMEM>>>(W2, root2, b2, out);
}

// round 10
// speedup vs baseline: 2.0172x; 1.1803x over previous
#include <cuda_runtime.h>
#include <cuda_bf16.h>
#include <cstdint>

#define N_NODES 20000
#define N_REL 32
#define HID 128
#define EMBD 16
#define N_EDGES 600000
#define NSEG (N_NODES * N_REL)    // 640000
#define SCAN_BLOCKS (NSEG / 1024) // 625 exactly

// ---------------- scratch (device globals, 16B-aligned; ~28 MB) ----------------
__device__ __align__(16) int   g_scnt[NSEG];
__device__ __align__(16) int   g_tmp[NSEG];
__device__ __align__(16) int   g_rowptr[NSEG + 1];
__device__ __align__(16) int   g_cursor[NSEG];
__device__ __align__(16) float g_inv[NSEG];
__device__ __align__(16) int   g_esrc[N_EDGES];     // (rel<<16)|src per edge, bucketed by segment
__device__ __align__(16) float g_h1[N_NODES * HID];
__device__ __align__(16) int   g_bsum[SCAN_BLOCKS];
__device__ __align__(16) int   g_bexcl[SCAN_BLOCKS];
// split-bf16 layer-2 weights, natural row-major [k][n]: 33 rels x [128][128]
__device__ __align__(16) __nv_bfloat16 g_wt_hi[33 * 128 * 128];
__device__ __align__(16) __nv_bfloat16 g_wt_lo[33 * 128 * 128];
__device__ int g_ei64;
__device__ int g_et64;

__device__ __forceinline__ int load_idx(const void* p, long long i, int is64) {
    return is64 ? (int)((const long long*)p)[i] : ((const int*)p)[i];
}

__device__ __forceinline__ uint32_t smem_u32(const void* p) {
    uint32_t a;
    asm("{ .reg .u64 t; cvta.to.shared.u64 t, %1; cvt.u32.u64 %0, t; }" : "=r"(a) : "l"(p));
    return a;
}

__device__ __forceinline__ uint32_t pack_bf2(float x, float y) {
    __nv_bfloat162 h = __floats2bfloat162_rn(x, y);
    return *(uint32_t*)&h;
}

__device__ __forceinline__ void ldsm_x4(uint32_t& r0, uint32_t& r1, uint32_t& r2, uint32_t& r3,
                                        uint32_t addr) {
    asm volatile("ldmatrix.sync.aligned.m8n8.x4.shared.b16 {%0,%1,%2,%3}, [%4];"
                 : "=r"(r0), "=r"(r1), "=r"(r2), "=r"(r3) : "r"(addr));
}
__device__ __forceinline__ void ldsm_x4_t(uint32_t& r0, uint32_t& r1, uint32_t& r2, uint32_t& r3,
                                          uint32_t addr) {
    asm volatile("ldmatrix.sync.aligned.m8n8.x4.trans.shared.b16 {%0,%1,%2,%3}, [%4];"
                 : "=r"(r0), "=r"(r1), "=r"(r2), "=r"(r3) : "r"(addr));
}
__device__ __forceinline__ void mma16816(float* c, uint32_t a0, uint32_t a1, uint32_t a2,
                                         uint32_t a3, uint32_t b0, uint32_t b1) {
    asm volatile(
        "mma.sync.aligned.m16n8k16.row.col.f32.bf16.bf16.f32 "
        "{%0,%1,%2,%3}, {%4,%5,%6,%7}, {%8,%9}, {%0,%1,%2,%3};"
        : "+f"(c[0]), "+f"(c[1]), "+f"(c[2]), "+f"(c[3])
        : "r"(a0), "r"(a1), "r"(a2), "r"(a3), "r"(b0), "r"(b1));
}

// ---------------- dtype detection (int32 vs int64 index arrays) ----------------
__global__ void k_detect(const int* __restrict__ ei, const int* __restrict__ et) {
    if (blockIdx.x == 0 && threadIdx.x == 0) {
        int a = 1, b = 1;
        for (int i = 0; i < 64; i++) if (ei[2 * i + 1] != 0) { a = 0; break; }
        for (int i = 0; i < 64; i++) if (et[2 * i + 1] != 0) { b = 0; break; }
        g_ei64 = a;
        g_et64 = b;
    }
}

// ---------------- preprocessing ----------------
__global__ void k_init() {
    int i0 = blockIdx.x * blockDim.x + threadIdx.x;
    int stride = gridDim.x * blockDim.x;
    for (int i = i0; i < NSEG; i += stride) g_scnt[i] = 0;
}

__global__ void k_count(const void* __restrict__ ei, const void* __restrict__ et) {
    int i0 = blockIdx.x * blockDim.x + threadIdx.x;
    int stride = gridDim.x * blockDim.x;
    int e64 = g_ei64, t64 = g_et64;
    for (int e = i0; e < N_EDGES; e += stride) {
        int dst = load_idx(ei, (long long)N_EDGES + e, e64);
        int r = load_idx(et, e, t64);
        if ((unsigned)dst >= N_NODES || (unsigned)r >= N_REL) continue;
        atomicAdd(&g_scnt[dst * N_REL + r], 1);
    }
}

__global__ void k_scan1() {
    __shared__ int sdata[1024];
    int tid = threadIdx.x;
    int i = blockIdx.x * 1024 + tid;
    int v = g_scnt[i];
    g_inv[i] = (v > 0) ? (1.0f / (float)v) : 0.0f;
    sdata[tid] = v;
    __syncthreads();
    for (int off = 1; off < 1024; off <<= 1) {
        int tmp = (tid >= off) ? sdata[tid - off] : 0;
        __syncthreads();
        sdata[tid] += tmp;
        __syncthreads();
    }
    g_tmp[i] = sdata[tid];
    if (tid == 1023) g_bsum[blockIdx.x] = sdata[1023];
}

__global__ void k_scan2() {
    __shared__ int sdata[1024];
    int tid = threadIdx.x;
    int v = (tid < SCAN_BLOCKS) ? g_bsum[tid] : 0;
    sdata[tid] = v;
    __syncthreads();
    for (int off = 1; off < 1024; off <<= 1) {
        int tmp = (tid >= off) ? sdata[tid - off] : 0;
        __syncthreads();
        sdata[tid] += tmp;
        __syncthreads();
    }
    if (tid < SCAN_BLOCKS) g_bexcl[tid] = sdata[tid] - v;
}

__global__ void k_scan3() {
    int i0 = blockIdx.x * blockDim.x + threadIdx.x;
    int stride = gridDim.x * blockDim.x;
    for (int i = i0; i < NSEG; i += stride) {
        int val = g_bexcl[i >> 10] + g_tmp[i];
        g_rowptr[i + 1] = val;
        g_cursor[i] = val - g_scnt[i];
    }
    if (i0 == 0) g_rowptr[0] = 0;
}

__global__ void k_bucket(const void* __restrict__ ei, const void* __restrict__ et) {
    int i0 = blockIdx.x * blockDim.x + threadIdx.x;
    int stride = gridDim.x * blockDim.x;
    int e64 = g_ei64, t64 = g_et64;
    for (int e = i0; e < N_EDGES; e += stride) {
        int src = load_idx(ei, e, e64);
        int dst = load_idx(ei, (long long)N_EDGES + e, e64);
        int r = load_idx(et, e, t64);
        if ((unsigned)src >= N_NODES || (unsigned)dst >= N_NODES || (unsigned)r >= N_REL) continue;
        int idx = atomicAdd(&g_cursor[dst * N_REL + r], 1);
        g_esrc[idx] = (r << 16) | src;
    }
}

// ---------------- precompute: split layer-2 weights to bf16 hi/lo, row-major [k][n] ----------
__global__ void k_wsplit(const float* __restrict__ W2, const float* __restrict__ root2) {
    int rel = blockIdx.x;
    const float* W = (rel < N_REL) ? (W2 + (size_t)rel * HID * HID) : root2;
    __nv_bfloat16* oh = g_wt_hi + (size_t)rel * HID * HID;
    __nv_bfloat16* ol = g_wt_lo + (size_t)rel * HID * HID;
    int t = threadIdx.x;
    for (int u = t; u < 2048; u += 256) {  // 2048 units of 8 contiguous values
        int base = u * 8;
        float4 w0 = *(const float4*)&W[base];
        float4 w1 = *(const float4*)&W[base + 4];
        float v[8] = {w0.x, w0.y, w0.z, w0.w, w1.x, w1.y, w1.z, w1.w};
        float l[8];
#pragma unroll
        for (int i = 0; i < 8; i++) {
            float h = __bfloat162float(__float2bfloat16_rn(v[i]));
            l[i] = v[i] - h;
        }
        *(uint4*)&oh[base] = make_uint4(pack_bf2(v[0], v[1]), pack_bf2(v[2], v[3]),
                                        pack_bf2(v[4], v[5]), pack_bf2(v[6], v[7]));
        *(uint4*)&ol[base] = make_uint4(pack_bf2(l[0], l[1]), pack_bf2(l[2], l[3]),
                                        pack_bf2(l[4], l[5]), pack_bf2(l[6], l[7]));
    }
}

// ==================== layer 1 (fp32 SIMT, unchanged — protected win) ====================
#define L1_AS 548
#define L1_SMEM ((32 * L1_AS + 32 * 132) * 4)

__global__ void __launch_bounds__(256) k_l1(const float* __restrict__ emb,
                                            const float* __restrict__ W1,
                                            const float* __restrict__ root1,
                                            const float* __restrict__ b1) {
    extern __shared__ float sm[];
    float* As = sm;
    float* Bs = sm + 32 * L1_AS;
    int n0 = blockIdx.x * 32;
    int t = threadIdx.x;
    int d = t >> 3, sub = t & 7, f0 = sub * 2;

    float4 z4 = make_float4(0.f, 0.f, 0.f, 0.f);
#pragma unroll
    for (int q = 0; q < 16; ++q)
        *(float4*)&As[d * L1_AS + sub * 64 + q * 4] = z4;
    __syncthreads();

    int base = (n0 + d) * N_REL;
    int s = g_rowptr[base], e = g_rowptr[base + N_REL];
    for (int j = s; j < e; ++j) {
        int p = g_esrc[j];
        int src = p & 0xFFFF, rel = p >> 16;
        float2 v = *(const float2*)&emb[src * EMBD + f0];
        As[d * L1_AS + rel * 16 + f0]     += v.x;
        As[d * L1_AS + rel * 16 + f0 + 1] += v.y;
    }
#pragma unroll 8
    for (int rel = 0; rel < N_REL; ++rel) {
        float iv = g_inv[base + rel];
        As[d * L1_AS + rel * 16 + f0]     *= iv;
        As[d * L1_AS + rel * 16 + f0 + 1] *= iv;
    }
    {
        float2 rv = *(const float2*)&emb[(n0 + d) * EMBD + f0];
        As[d * L1_AS + 512 + f0]     = rv.x;
        As[d * L1_AS + 512 + f0 + 1] = rv.y;
    }

    int d0 = (t >> 5) * 4;
    int col0 = (t & 31) * 4;
    float acc[4][4];
#pragma unroll
    for (int i = 0; i < 4; i++)
#pragma unroll
        for (int j = 0; j < 4; j++) acc[i][j] = 0.f;

    for (int kc = 0; kc <= 16; ++kc) {
        int krows = (kc < 16) ? 32 : 16;
        const float* Bsrc = (kc < 16) ? (W1 + (size_t)(kc * 32) * HID) : root1;
        __syncthreads();
        {
            int row = t >> 3, c0f = (t & 7) * 16;
            if (row < krows) {
#pragma unroll
                for (int q = 0; q < 4; ++q)
                    *(float4*)&Bs[row * 132 + c0f + q * 4] =
                        *(const float4*)&Bsrc[(size_t)row * HID + c0f + q * 4];
            }
        }
        __syncthreads();
        int kbase = kc * 32;
        int nk4 = krows >> 2;
#pragma unroll 4
        for (int k4 = 0; k4 < nk4; ++k4) {
            int kb = kbase + k4 * 4;
            float4 a0 = *(const float4*)&As[(d0 + 0) * L1_AS + kb];
            float4 a1 = *(const float4*)&As[(d0 + 1) * L1_AS + kb];
            float4 a2 = *(const float4*)&As[(d0 + 2) * L1_AS + kb];
            float4 a3 = *(const float4*)&As[(d0 + 3) * L1_AS + kb];
            int kk = k4 * 4;
            float4 b0 = *(const float4*)&Bs[(kk + 0) * 132 + col0];
            float4 b1v = *(const float4*)&Bs[(kk + 1) * 132 + col0];
            float4 b2v = *(const float4*)&Bs[(kk + 2) * 132 + col0];
            float4 b3v = *(const float4*)&Bs[(kk + 3) * 132 + col0];
#define L1ROW(i, av)                                                                   \
            acc[i][0] += av.x * b0.x;  acc[i][1] += av.x * b0.y;                       \
            acc[i][2] += av.x * b0.z;  acc[i][3] += av.x * b0.w;                       \
            acc[i][0] += av.y * b1v.x; acc[i][1] += av.y * b1v.y;                      \
            acc[i][2] += av.y * b1v.z; acc[i][3] += av.y * b1v.w;                      \
            acc[i][0] += av.z * b2v.x; acc[i][1] += av.z * b2v.y;                      \
            acc[i][2] += av.z * b2v.z; acc[i][3] += av.z * b2v.w;                      \
            acc[i][0] += av.w * b3v.x; acc[i][1] += av.w * b3v.y;                      \
            acc[i][2] += av.w * b3v.z; acc[i][3] += av.w * b3v.w;
            L1ROW(0, a0) L1ROW(1, a1) L1ROW(2, a2) L1ROW(3, a3)
#undef L1ROW
        }
    }

    float4 bb = *(const float4*)&b1[col0];
#pragma unroll
    for (int i = 0; i < 4; ++i) {
        int n = n0 + d0 + i;
        float4 v = make_float4(fmaxf(acc[i][0] + bb.x, 0.f), fmaxf(acc[i][1] + bb.y, 0.f),
                               fmaxf(acc[i][2] + bb.z, 0.f), fmaxf(acc[i][3] + bb.w, 0.f));
        *(float4*)&g_h1[(size_t)n * HID + col0] = v;
    }
}

// ==================== layer 2: mma.sync bf16-split GEMM ====================
// Block = 128 dst x 128 cols, 256 threads (8 warps, each 32 rows x 64 cols).
// Per rel: gather A fp32 -> split hi/lo bf16 smem [128][136]; copy B hi/lo -> smem;
// 3 passes (ah*bh, ah*bl, al*bh) of mma.m16n8k16, fp32 acc in registers across 33 rels.
#define L2_STRIDE 136
#define L2_TILE (128 * L2_STRIDE * 2)   // 34816 bytes per bf16 tile
#define SM_AHI 0
#define SM_ALO (L2_TILE)
#define SM_BHI (2 * L2_TILE)
#define SM_BLO (3 * L2_TILE)
#define L2T_SMEM (4 * L2_TILE)          // 139264 bytes

__global__ void __launch_bounds__(256, 1) k_l2t(const float* __restrict__ b2,
                                                float* __restrict__ out) {
    extern __shared__ char smc[];
    __nv_bfloat16* sA_hi = (__nv_bfloat16*)(smc + SM_AHI);
    __nv_bfloat16* sA_lo = (__nv_bfloat16*)(smc + SM_ALO);
    uint32_t sb = smem_u32(smc);
    int t = threadIdx.x, wid = t >> 5, lane = t & 31;
    int n0 = blockIdx.x * 128;

    // gather roles
    int dg = t >> 3, sub = t & 7;        // 32 dst-slots x 8 col-groups(16 cols)
    // compute roles
    int mrow = (wid & 3) * 32, ncol = (wid >> 2) * 64;
    int l15 = lane & 15, lhi = (lane >> 4) << 3;   // ldmatrix address pieces
    int grp = lane >> 2, tg = lane & 3;            // fragment element pieces

    float acc[2][8][4];
#pragma unroll
    for (int mi = 0; mi < 2; mi++)
#pragma unroll
        for (int ni = 0; ni < 8; ni++)
#pragma unroll
            for (int q = 0; q < 4; q++) acc[mi][ni][q] = 0.f;

    for (int rel = 0; rel <= N_REL; ++rel) {
        __syncthreads();  // previous pass's fragment loads done before overwrite
        // ---- B copy: global [128][128] bf16 -> smem [128][136] ----
        {
            const uint4* sh = (const uint4*)(g_wt_hi + (size_t)rel * HID * HID);
            const uint4* sl = (const uint4*)(g_wt_lo + (size_t)rel * HID * HID);
#pragma unroll
            for (int i = 0; i < 8; ++i) {
                int u = t + i * 256;           // unit of 8 bf16
                int row = u >> 4, c8 = (u & 15) * 8;
                int doff = row * L2_STRIDE + c8;
                *(uint4*)(smc + SM_BHI + doff * 2) = sh[u];
                *(uint4*)(smc + SM_BLO + doff * 2) = sl[u];
            }
        }
        // ---- A gather + split: 4 dsts per thread, 16 cols each ----
        for (int dd = 0; dd < 4; ++dd) {
            int d = dg + dd * 32;
            int n = n0 + d;
            float a[16];
#pragma unroll
            for (int i = 0; i < 16; i++) a[i] = 0.f;
            if (n < N_NODES) {
                if (rel < N_REL) {
                    int seg = n * N_REL + rel;
                    int s = g_rowptr[seg], e = g_rowptr[seg + 1];
                    for (int j = s; j < e; ++j) {
                        int src = g_esrc[j] & 0xFFFF;
                        const float* hp = &g_h1[(size_t)src * HID + sub * 16];
                        float4 v0 = *(const float4*)(hp + 0);
                        float4 v1 = *(const float4*)(hp + 4);
                        float4 v2 = *(const float4*)(hp + 8);
                        float4 v3 = *(const float4*)(hp + 12);
                        a[0] += v0.x; a[1] += v0.y; a[2] += v0.z; a[3] += v0.w;
                        a[4] += v1.x; a[5] += v1.y; a[6] += v1.z; a[7] += v1.w;
                        a[8] += v2.x; a[9] += v2.y; a[10] += v2.z; a[11] += v2.w;
                        a[12] += v3.x; a[13] += v3.y; a[14] += v3.z; a[15] += v3.w;
                    }
                    float iv = g_inv[seg];
#pragma unroll
                    for (int i = 0; i < 16; i++) a[i] *= iv;
                } else {  // root term
                    const float* hp = &g_h1[(size_t)n * HID + sub * 16];
                    float4 v0 = *(const float4*)(hp + 0);
                    float4 v1 = *(const float4*)(hp + 4);
                    float4 v2 = *(const float4*)(hp + 8);
                    float4 v3 = *(const float4*)(hp + 12);
                    a[0] = v0.x; a[1] = v0.y; a[2] = v0.z; a[3] = v0.w;
                    a[4] = v1.x; a[5] = v1.y; a[6] = v1.z; a[7] = v1.w;
                    a[8] = v2.x; a[9] = v2.y; a[10] = v2.z; a[11] = v2.w;
                    a[12] = v3.x; a[13] = v3.y; a[14] = v3.z; a[15] = v3.w;
                }
            }
            float lo[16];
#pragma unroll
            for (int i = 0; i < 16; i++) {
                float h = __bfloat162float(__float2bfloat16_rn(a[i]));
                lo[i] = a[i] - h;
            }
            int aoff = d * L2_STRIDE + sub * 16;
#pragma unroll
            for (int q = 0; q < 2; ++q) {
                *(uint4*)&sA_hi[aoff + q * 8] =
                    make_uint4(pack_bf2(a[q * 8 + 0], a[q * 8 + 1]), pack_bf2(a[q * 8 + 2], a[q * 8 + 3]),
                               pack_bf2(a[q * 8 + 4], a[q * 8 + 5]), pack_bf2(a[q * 8 + 6], a[q * 8 + 7]));
                *(uint4*)&sA_lo[aoff + q * 8] =
                    make_uint4(pack_bf2(lo[q * 8 + 0], lo[q * 8 + 1]), pack_bf2(lo[q * 8 + 2], lo[q * 8 + 3]),
                               pack_bf2(lo[q * 8 + 4], lo[q * 8 + 5]), pack_bf2(lo[q * 8 + 6], lo[q * 8 + 7]));
            }
        }
        __syncthreads();
        // ---- MMA: 3 passes over [128 rows] x [128 cols] x K=128 ----
#pragma unroll
        for (int pass = 0; pass < 3; ++pass) {
            uint32_t abase = sb + ((pass == 2) ? SM_ALO : SM_AHI);
            uint32_t bbase = sb + ((pass == 1) ? SM_BLO : SM_BHI);
#pragma unroll
            for (int ks = 0; ks < 8; ++ks) {
                int k0 = ks * 16;
                uint32_t af[2][4];
#pragma unroll
                for (int mi = 0; mi < 2; ++mi) {
                    uint32_t addr = abase + ((mrow + mi * 16 + l15) * L2_STRIDE + k0 + lhi) * 2;
                    ldsm_x4(af[mi][0], af[mi][1], af[mi][2], af[mi][3], addr);
                }
#pragma unroll
                for (int np = 0; np < 4; ++np) {
                    uint32_t baddr = bbase + ((k0 + l15) * L2_STRIDE + ncol + np * 16 + lhi) * 2;
                    uint32_t b0, b1, b2r, b3;
                    ldsm_x4_t(b0, b1, b2r, b3, baddr);
#pragma unroll
                    for (int mi = 0; mi < 2; ++mi) {
                        mma16816(acc[mi][np * 2 + 0], af[mi][0], af[mi][1], af[mi][2], af[mi][3], b0, b1);
                        mma16816(acc[mi][np * 2 + 1], af[mi][0], af[mi][1], af[mi][2], af[mi][3], b2r, b3);
                    }
                }
            }
        }
    }

    // ---- epilogue: + b2 -> out ----
#pragma unroll
    for (int mi = 0; mi < 2; ++mi) {
        int r0 = n0 + mrow + mi * 16 + grp;
#pragma unroll
        for (int ni = 0; ni < 8; ++ni) {
            int col = ncol + ni * 8 + tg * 2;
            float2 bb = *(const float2*)&b2[col];
            if (r0 < N_NODES)
                *(float2*)&out[(size_t)r0 * HID + col] =
                    make_float2(acc[mi][ni][0] + bb.x, acc[mi][ni][1] + bb.y);
            if (r0 + 8 < N_NODES)
                *(float2*)&out[(size_t)(r0 + 8) * HID + col] =
                    make_float2(acc[mi][ni][2] + bb.x, acc[mi][ni][3] + bb.y);
        }
    }
}

// ---------------- launch ----------------
extern "C" void kernel_launch(void* const* d_in, const int* in_sizes, int n_in,
                              void* d_out, int out_size) {
    const void* edge_index = d_in[0];
    const void* edge_type = d_in[1];
    const float* node_emb = (const float*)d_in[2];
    const float* W1 = (const float*)d_in[3];
    const float* root1 = (const float*)d_in[4];
    const float* b1 = (const float*)d_in[5];
    const float* W2 = (const float*)d_in[6];
    const float* root2 = (const float*)d_in[7];
    const float* b2 = (const float*)d_in[8];
    float* out = (float*)d_out;

    static int attr_done = 0;
    if (!attr_done) {
        cudaFuncSetAttribute(k_l1, cudaFuncAttributeMaxDynamicSharedMemorySize, L1_SMEM);
        cudaFuncSetAttribute(k_l2t, cudaFuncAttributeMaxDynamicSharedMemorySize, L2T_SMEM);
        attr_done = 1;
    }

    k_detect<<<1, 32>>>((const int*)edge_index, (const int*)edge_type);

    k_init<<<640, 1024>>>();
    k_count<<<1172, 256>>>(edge_index, edge_type);
    k_scan1<<<SCAN_BLOCKS, 1024>>>();
    k_scan2<<<1, 1024>>>();
    k_scan3<<<640, 1024>>>();
    k_bucket<<<1172, 256>>>(edge_index, edge_type);
    k_wsplit<<<33, 256>>>(W2, root2);

    k_l1<<<625, 256, L1_SMEM>>>(node_emb, W1, root1, b1);
    k_l2t<<<157, 256, L2T_SMEM>>>(b2, out);
}

// round 11
// speedup vs baseline: 2.1212x; 1.0515x over previous
#include <cuda_runtime.h>
#include <cuda_bf16.h>
#include <cstdint>

#define N_NODES 20000
#define N_REL 32
#define HID 128
#define EMBD 16
#define N_EDGES 600000
#define NSEG (N_NODES * N_REL)    // 640000
#define SCAN_BLOCKS (NSEG / 1024) // 625 exactly

// ---------------- scratch (device globals, 16B-aligned; ~28 MB) ----------------
__device__ __align__(16) int   g_scnt[NSEG];
__device__ __align__(16) int   g_tmp[NSEG];
__device__ __align__(16) int   g_rowptr[NSEG + 1];
__device__ __align__(16) int   g_cursor[NSEG];
__device__ __align__(16) float g_inv[NSEG];
__device__ __align__(16) int   g_esrc[N_EDGES];     // (rel<<16)|src per edge, bucketed by segment
__device__ __align__(16) float g_h1[N_NODES * HID];
__device__ __align__(16) int   g_bsum[SCAN_BLOCKS];
__device__ __align__(16) int   g_bexcl[SCAN_BLOCKS];
// split-bf16 layer-2 weights, natural row-major [k][n]: 33 rels x [128][128]
__device__ __align__(16) __nv_bfloat16 g_wt_hi[33 * 128 * 128];
__device__ __align__(16) __nv_bfloat16 g_wt_lo[33 * 128 * 128];
__device__ int g_ei64;
__device__ int g_et64;

__device__ __forceinline__ int load_idx(const void* p, long long i, int is64) {
    return is64 ? (int)((const long long*)p)[i] : ((const int*)p)[i];
}

__device__ __forceinline__ uint32_t smem_u32(const void* p) {
    uint32_t a;
    asm("{ .reg .u64 t; cvta.to.shared.u64 t, %1; cvt.u32.u64 %0, t; }" : "=r"(a) : "l"(p));
    return a;
}

__device__ __forceinline__ uint32_t pack_bf2(float x, float y) {
    __nv_bfloat162 h = __floats2bfloat162_rn(x, y);
    return *(uint32_t*)&h;
}

__device__ __forceinline__ void ldsm_x4(uint32_t& r0, uint32_t& r1, uint32_t& r2, uint32_t& r3,
                                        uint32_t addr) {
    asm volatile("ldmatrix.sync.aligned.m8n8.x4.shared.b16 {%0,%1,%2,%3}, [%4];"
                 : "=r"(r0), "=r"(r1), "=r"(r2), "=r"(r3) : "r"(addr));
}
__device__ __forceinline__ void ldsm_x4_t(uint32_t& r0, uint32_t& r1, uint32_t& r2, uint32_t& r3,
                                          uint32_t addr) {
    asm volatile("ldmatrix.sync.aligned.m8n8.x4.trans.shared.b16 {%0,%1,%2,%3}, [%4];"
                 : "=r"(r0), "=r"(r1), "=r"(r2), "=r"(r3) : "r"(addr));
}
__device__ __forceinline__ void mma16816(float* c, uint32_t a0, uint32_t a1, uint32_t a2,
                                         uint32_t a3, uint32_t b0, uint32_t b1) {
    asm volatile(
        "mma.sync.aligned.m16n8k16.row.col.f32.bf16.bf16.f32 "
        "{%0,%1,%2,%3}, {%4,%5,%6,%7}, {%8,%9}, {%0,%1,%2,%3};"
        : "+f"(c[0]), "+f"(c[1]), "+f"(c[2]), "+f"(c[3])
        : "r"(a0), "r"(a1), "r"(a2), "r"(a3), "r"(b0), "r"(b1));
}

// ---------------- dtype detection (int32 vs int64 index arrays) ----------------
__global__ void k_detect(const int* __restrict__ ei, const int* __restrict__ et) {
    if (blockIdx.x == 0 && threadIdx.x == 0) {
        int a = 1, b = 1;
        for (int i = 0; i < 64; i++) if (ei[2 * i + 1] != 0) { a = 0; break; }
        for (int i = 0; i < 64; i++) if (et[2 * i + 1] != 0) { b = 0; break; }
        g_ei64 = a;
        g_et64 = b;
    }
}

// ---------------- preprocessing ----------------
__global__ void k_init() {
    int i0 = blockIdx.x * blockDim.x + threadIdx.x;
    int stride = gridDim.x * blockDim.x;
    for (int i = i0; i < NSEG; i += stride) g_scnt[i] = 0;
}

__global__ void k_count(const void* __restrict__ ei, const void* __restrict__ et) {
    int i0 = blockIdx.x * blockDim.x + threadIdx.x;
    int stride = gridDim.x * blockDim.x;
    int e64 = g_ei64, t64 = g_et64;
    for (int e = i0; e < N_EDGES; e += stride) {
        int dst = load_idx(ei, (long long)N_EDGES + e, e64);
        int r = load_idx(et, e, t64);
        if ((unsigned)dst >= N_NODES || (unsigned)r >= N_REL) continue;
        atomicAdd(&g_scnt[dst * N_REL + r], 1);
    }
}

__global__ void k_scan1() {
    __shared__ int sdata[1024];
    int tid = threadIdx.x;
    int i = blockIdx.x * 1024 + tid;
    int v = g_scnt[i];
    g_inv[i] = (v > 0) ? (1.0f / (float)v) : 0.0f;
    sdata[tid] = v;
    __syncthreads();
    for (int off = 1; off < 1024; off <<= 1) {
        int tmp = (tid >= off) ? sdata[tid - off] : 0;
        __syncthreads();
        sdata[tid] += tmp;
        __syncthreads();
    }
    g_tmp[i] = sdata[tid];
    if (tid == 1023) g_bsum[blockIdx.x] = sdata[1023];
}

__global__ void k_scan2() {
    __shared__ int sdata[1024];
    int tid = threadIdx.x;
    int v = (tid < SCAN_BLOCKS) ? g_bsum[tid] : 0;
    sdata[tid] = v;
    __syncthreads();
    for (int off = 1; off < 1024; off <<= 1) {
        int tmp = (tid >= off) ? sdata[tid - off] : 0;
        __syncthreads();
        sdata[tid] += tmp;
        __syncthreads();
    }
    if (tid < SCAN_BLOCKS) g_bexcl[tid] = sdata[tid] - v;
}

__global__ void k_scan3() {
    int i0 = blockIdx.x * blockDim.x + threadIdx.x;
    int stride = gridDim.x * blockDim.x;
    for (int i = i0; i < NSEG; i += stride) {
        int val = g_bexcl[i >> 10] + g_tmp[i];
        g_rowptr[i + 1] = val;
        g_cursor[i] = val - g_scnt[i];
    }
    if (i0 == 0) g_rowptr[0] = 0;
}

__global__ void k_bucket(const void* __restrict__ ei, const void* __restrict__ et) {
    int i0 = blockIdx.x * blockDim.x + threadIdx.x;
    int stride = gridDim.x * blockDim.x;
    int e64 = g_ei64, t64 = g_et64;
    for (int e = i0; e < N_EDGES; e += stride) {
        int src = load_idx(ei, e, e64);
        int dst = load_idx(ei, (long long)N_EDGES + e, e64);
        int r = load_idx(et, e, t64);
        if ((unsigned)src >= N_NODES || (unsigned)dst >= N_NODES || (unsigned)r >= N_REL) continue;
        int idx = atomicAdd(&g_cursor[dst * N_REL + r], 1);
        g_esrc[idx] = (r << 16) | src;
    }
}

// ---------------- precompute: split layer-2 weights to bf16 hi/lo, row-major [k][n] ----------
__global__ void k_wsplit(const float* __restrict__ W2, const float* __restrict__ root2) {
    int rel = blockIdx.x;
    const float* W = (rel < N_REL) ? (W2 + (size_t)rel * HID * HID) : root2;
    __nv_bfloat16* oh = g_wt_hi + (size_t)rel * HID * HID;
    __nv_bfloat16* ol = g_wt_lo + (size_t)rel * HID * HID;
    int t = threadIdx.x;
    for (int u = t; u < 2048; u += 256) {  // 2048 units of 8 contiguous values
        int base = u * 8;
        float4 w0 = *(const float4*)&W[base];
        float4 w1 = *(const float4*)&W[base + 4];
        float v[8] = {w0.x, w0.y, w0.z, w0.w, w1.x, w1.y, w1.z, w1.w};
        float l[8];
#pragma unroll
        for (int i = 0; i < 8; i++) {
            float h = __bfloat162float(__float2bfloat16_rn(v[i]));
            l[i] = v[i] - h;
        }
        *(uint4*)&oh[base] = make_uint4(pack_bf2(v[0], v[1]), pack_bf2(v[2], v[3]),
                                        pack_bf2(v[4], v[5]), pack_bf2(v[6], v[7]));
        *(uint4*)&ol[base] = make_uint4(pack_bf2(l[0], l[1]), pack_bf2(l[2], l[3]),
                                        pack_bf2(l[4], l[5]), pack_bf2(l[6], l[7]));
    }
}

// ==================== layer 1 (fp32 SIMT, unchanged — protected win) ====================
#define L1_AS 548
#define L1_SMEM ((32 * L1_AS + 32 * 132) * 4)

__global__ void __launch_bounds__(256) k_l1(const float* __restrict__ emb,
                                            const float* __restrict__ W1,
                                            const float* __restrict__ root1,
                                            const float* __restrict__ b1) {
    extern __shared__ float sm[];
    float* As = sm;
    float* Bs = sm + 32 * L1_AS;
    int n0 = blockIdx.x * 32;
    int t = threadIdx.x;
    int d = t >> 3, sub = t & 7, f0 = sub * 2;

    float4 z4 = make_float4(0.f, 0.f, 0.f, 0.f);
#pragma unroll
    for (int q = 0; q < 16; ++q)
        *(float4*)&As[d * L1_AS + sub * 64 + q * 4] = z4;
    __syncthreads();

    int base = (n0 + d) * N_REL;
    int s = g_rowptr[base], e = g_rowptr[base + N_REL];
    for (int j = s; j < e; ++j) {
        int p = g_esrc[j];
        int src = p & 0xFFFF, rel = p >> 16;
        float2 v = *(const float2*)&emb[src * EMBD + f0];
        As[d * L1_AS + rel * 16 + f0]     += v.x;
        As[d * L1_AS + rel * 16 + f0 + 1] += v.y;
    }
#pragma unroll 8
    for (int rel = 0; rel < N_REL; ++rel) {
        float iv = g_inv[base + rel];
        As[d * L1_AS + rel * 16 + f0]     *= iv;
        As[d * L1_AS + rel * 16 + f0 + 1] *= iv;
    }
    {
        float2 rv = *(const float2*)&emb[(n0 + d) * EMBD + f0];
        As[d * L1_AS + 512 + f0]     = rv.x;
        As[d * L1_AS + 512 + f0 + 1] = rv.y;
    }

    int d0 = (t >> 5) * 4;
    int col0 = (t & 31) * 4;
    float acc[4][4];
#pragma unroll
    for (int i = 0; i < 4; i++)
#pragma unroll
        for (int j = 0; j < 4; j++) acc[i][j] = 0.f;

    for (int kc = 0; kc <= 16; ++kc) {
        int krows = (kc < 16) ? 32 : 16;
        const float* Bsrc = (kc < 16) ? (W1 + (size_t)(kc * 32) * HID) : root1;
        __syncthreads();
        {
            int row = t >> 3, c0f = (t & 7) * 16;
            if (row < krows) {
#pragma unroll
                for (int q = 0; q < 4; ++q)
                    *(float4*)&Bs[row * 132 + c0f + q * 4] =
                        *(const float4*)&Bsrc[(size_t)row * HID + c0f + q * 4];
            }
        }
        __syncthreads();
        int kbase = kc * 32;
        int nk4 = krows >> 2;
#pragma unroll 4
        for (int k4 = 0; k4 < nk4; ++k4) {
            int kb = kbase + k4 * 4;
            float4 a0 = *(const float4*)&As[(d0 + 0) * L1_AS + kb];
            float4 a1 = *(const float4*)&As[(d0 + 1) * L1_AS + kb];
            float4 a2 = *(const float4*)&As[(d0 + 2) * L1_AS + kb];
            float4 a3 = *(const float4*)&As[(d0 + 3) * L1_AS + kb];
            int kk = k4 * 4;
            float4 b0 = *(const float4*)&Bs[(kk + 0) * 132 + col0];
            float4 b1v = *(const float4*)&Bs[(kk + 1) * 132 + col0];
            float4 b2v = *(const float4*)&Bs[(kk + 2) * 132 + col0];
            float4 b3v = *(const float4*)&Bs[(kk + 3) * 132 + col0];
#define L1ROW(i, av)                                                                   \
            acc[i][0] += av.x * b0.x;  acc[i][1] += av.x * b0.y;                       \
            acc[i][2] += av.x * b0.z;  acc[i][3] += av.x * b0.w;                       \
            acc[i][0] += av.y * b1v.x; acc[i][1] += av.y * b1v.y;                      \
            acc[i][2] += av.y * b1v.z; acc[i][3] += av.y * b1v.w;                      \
            acc[i][0] += av.z * b2v.x; acc[i][1] += av.z * b2v.y;                      \
            acc[i][2] += av.z * b2v.z; acc[i][3] += av.z * b2v.w;                      \
            acc[i][0] += av.w * b3v.x; acc[i][1] += av.w * b3v.y;                      \
            acc[i][2] += av.w * b3v.z; acc[i][3] += av.w * b3v.w;
            L1ROW(0, a0) L1ROW(1, a1) L1ROW(2, a2) L1ROW(3, a3)
#undef L1ROW
        }
    }

    float4 bb = *(const float4*)&b1[col0];
#pragma unroll
    for (int i = 0; i < 4; ++i) {
        int n = n0 + d0 + i;
        float4 v = make_float4(fmaxf(acc[i][0] + bb.x, 0.f), fmaxf(acc[i][1] + bb.y, 0.f),
                               fmaxf(acc[i][2] + bb.z, 0.f), fmaxf(acc[i][3] + bb.w, 0.f));
        *(float4*)&g_h1[(size_t)n * HID + col0] = v;
    }
}

// ==================== layer 2: pipelined mma.sync bf16-split GEMM ====================
// Block = 128 dst x 128 cols, 256 threads (8 warps, each 32 rows x 64 cols).
// Software pipeline: gather A(rel+1) into ping-pong buffer (no barrier), then mma(rel);
// one sync per iteration, then stream B(rel+1). Merged-pass mma: per k-step load
// A_hi/A_lo + B_hi/B_lo fragments once, issue all 3 combos (ah*bh, al*bh, ah*bl).
#define L2_STRIDE 136
#define L2_TILE (128 * L2_STRIDE * 2)   // 34816 bytes per bf16 tile
// smem: bufA[b] hi at b*2T, lo at b*2T+T (b=0,1); B hi at 4T, lo at 5T
#define SM_BHI (4 * L2_TILE)
#define SM_BLO (5 * L2_TILE)
#define L2T_SMEM (6 * L2_TILE)          // 208896 bytes

__device__ __forceinline__ void l2_copy_b(char* smc, int rel, int t) {
    const uint4* sh = (const uint4*)(g_wt_hi + (size_t)rel * HID * HID);
    const uint4* sl = (const uint4*)(g_wt_lo + (size_t)rel * HID * HID);
#pragma unroll
    for (int i = 0; i < 8; ++i) {
        int u = t + i * 256;            // unit of 8 bf16
        int row = u >> 4, c8 = (u & 15) * 8;
        int doff = row * L2_STRIDE + c8;
        *(uint4*)(smc + SM_BHI + doff * 2) = sh[u];
        *(uint4*)(smc + SM_BLO + doff * 2) = sl[u];
    }
}

__device__ __forceinline__ void l2_gather(char* abase_hi, char* abase_lo, int rel,
                                          int n0, int dg, int sub) {
    __nv_bfloat16* sA_hi = (__nv_bfloat16*)abase_hi;
    __nv_bfloat16* sA_lo = (__nv_bfloat16*)abase_lo;
    for (int dd = 0; dd < 4; ++dd) {
        int d = dg + dd * 32;
        int n = n0 + d;
        float a[16];
#pragma unroll
        for (int i = 0; i < 16; i++) a[i] = 0.f;
        if (n < N_NODES) {
            if (rel < N_REL) {
                int seg = n * N_REL + rel;
                int s = g_rowptr[seg], e = g_rowptr[seg + 1];
                for (int j = s; j < e; ++j) {
                    int src = g_esrc[j] & 0xFFFF;
                    const float* hp = &g_h1[(size_t)src * HID + sub * 16];
                    float4 v0 = *(const float4*)(hp + 0);
                    float4 v1 = *(const float4*)(hp + 4);
                    float4 v2 = *(const float4*)(hp + 8);
                    float4 v3 = *(const float4*)(hp + 12);
                    a[0] += v0.x; a[1] += v0.y; a[2] += v0.z; a[3] += v0.w;
                    a[4] += v1.x; a[5] += v1.y; a[6] += v1.z; a[7] += v1.w;
                    a[8] += v2.x; a[9] += v2.y; a[10] += v2.z; a[11] += v2.w;
                    a[12] += v3.x; a[13] += v3.y; a[14] += v3.z; a[15] += v3.w;
                }
                float iv = g_inv[seg];
#pragma unroll
                for (int i = 0; i < 16; i++) a[i] *= iv;
            } else {  // root term
                const float* hp = &g_h1[(size_t)n * HID + sub * 16];
                float4 v0 = *(const float4*)(hp + 0);
                float4 v1 = *(const float4*)(hp + 4);
                float4 v2 = *(const float4*)(hp + 8);
                float4 v3 = *(const float4*)(hp + 12);
                a[0] = v0.x; a[1] = v0.y; a[2] = v0.z; a[3] = v0.w;
                a[4] = v1.x; a[5] = v1.y; a[6] = v1.z; a[7] = v1.w;
                a[8] = v2.x; a[9] = v2.y; a[10] = v2.z; a[11] = v2.w;
                a[12] = v3.x; a[13] = v3.y; a[14] = v3.z; a[15] = v3.w;
            }
        }
        float lo[16];
#pragma unroll
        for (int i = 0; i < 16; i++) {
            float h = __bfloat162float(__float2bfloat16_rn(a[i]));
            lo[i] = a[i] - h;
        }
        int aoff = d * L2_STRIDE + sub * 16;
#pragma unroll
        for (int q = 0; q < 2; ++q) {
            *(uint4*)&sA_hi[aoff + q * 8] =
                make_uint4(pack_bf2(a[q * 8 + 0], a[q * 8 + 1]), pack_bf2(a[q * 8 + 2], a[q * 8 + 3]),
                           pack_bf2(a[q * 8 + 4], a[q * 8 + 5]), pack_bf2(a[q * 8 + 6], a[q * 8 + 7]));
            *(uint4*)&sA_lo[aoff + q * 8] =
                make_uint4(pack_bf2(lo[q * 8 + 0], lo[q * 8 + 1]), pack_bf2(lo[q * 8 + 2], lo[q * 8 + 3]),
                           pack_bf2(lo[q * 8 + 4], lo[q * 8 + 5]), pack_bf2(lo[q * 8 + 6], lo[q * 8 + 7]));
        }
    }
}

__global__ void __launch_bounds__(256, 1) k_l2t(const float* __restrict__ b2,
                                                float* __restrict__ out) {
    extern __shared__ char smc[];
    uint32_t sb = smem_u32(smc);
    int t = threadIdx.x, wid = t >> 5, lane = t & 31;
    int n0 = blockIdx.x * 128;

    // gather roles
    int dg = t >> 3, sub = t & 7;        // 32 dst-slots x 8 col-groups(16 cols)
    // compute roles
    int mrow = (wid & 3) * 32, ncol = (wid >> 2) * 64;
    int l15 = lane & 15, lhi = (lane >> 4) << 3;   // ldmatrix address pieces
    int grp = lane >> 2, tg = lane & 3;            // fragment element pieces

    float acc[2][8][4];
#pragma unroll
    for (int mi = 0; mi < 2; mi++)
#pragma unroll
        for (int ni = 0; ni < 8; ni++)
#pragma unroll
            for (int q = 0; q < 4; q++) acc[mi][ni][q] = 0.f;

    // prologue: B(0) + A(0) into buffer 0
    l2_copy_b(smc, 0, t);
    l2_gather(smc + 0, smc + L2_TILE, 0, n0, dg, sub);
    __syncthreads();

    for (int rel = 0; rel <= N_REL; ++rel) {
        // ---- gather next relation into the other A buffer (no barrier before mma) ----
        if (rel < N_REL) {
            int nb = (rel + 1) & 1;
            l2_gather(smc + nb * 2 * L2_TILE, smc + nb * 2 * L2_TILE + L2_TILE,
                      rel + 1, n0, dg, sub);
        }
        // ---- MMA(rel) from current A buffer + B in smem ----
        {
            uint32_t ahib = sb + (rel & 1) * 2 * L2_TILE;
            uint32_t alob = ahib + L2_TILE;
            uint32_t bhib = sb + SM_BHI, blob = sb + SM_BLO;
#pragma unroll
            for (int ks = 0; ks < 8; ++ks) {
                int k0 = ks * 16;
                uint32_t ah[2][4], al[2][4];
#pragma unroll
                for (int mi = 0; mi < 2; ++mi) {
                    uint32_t rowoff = ((mrow + mi * 16 + l15) * L2_STRIDE + k0 + lhi) * 2;
                    ldsm_x4(ah[mi][0], ah[mi][1], ah[mi][2], ah[mi][3], ahib + rowoff);
                    ldsm_x4(al[mi][0], al[mi][1], al[mi][2], al[mi][3], alob + rowoff);
                }
#pragma unroll
                for (int np = 0; np < 4; ++np) {
                    uint32_t boff = ((k0 + l15) * L2_STRIDE + ncol + np * 16 + lhi) * 2;
                    uint32_t bh0, bh1, bh2, bh3;
                    ldsm_x4_t(bh0, bh1, bh2, bh3, bhib + boff);
#pragma unroll
                    for (int mi = 0; mi < 2; ++mi) {
                        mma16816(acc[mi][np * 2 + 0], ah[mi][0], ah[mi][1], ah[mi][2], ah[mi][3], bh0, bh1);
                        mma16816(acc[mi][np * 2 + 1], ah[mi][0], ah[mi][1], ah[mi][2], ah[mi][3], bh2, bh3);
                        mma16816(acc[mi][np * 2 + 0], al[mi][0], al[mi][1], al[mi][2], al[mi][3], bh0, bh1);
                        mma16816(acc[mi][np * 2 + 1], al[mi][0], al[mi][1], al[mi][2], al[mi][3], bh2, bh3);
                    }
                    uint32_t bl0, bl1, bl2, bl3;
                    ldsm_x4_t(bl0, bl1, bl2, bl3, blob + boff);
#pragma unroll
                    for (int mi = 0; mi < 2; ++mi) {
                        mma16816(acc[mi][np * 2 + 0], ah[mi][0], ah[mi][1], ah[mi][2], ah[mi][3], bl0, bl1);
                        mma16816(acc[mi][np * 2 + 1], ah[mi][0], ah[mi][1], ah[mi][2], ah[mi][3], bl2, bl3);
                    }
                }
            }
        }
        __syncthreads();   // mma(rel) + gather(rel+1) complete everywhere
        if (rel < N_REL) {
            l2_copy_b(smc, rel + 1, t);
            __syncthreads();  // B(rel+1) visible before next mma
        }
    }

    // ---- epilogue: + b2 -> out ----
#pragma unroll
    for (int mi = 0; mi < 2; ++mi) {
        int r0 = n0 + mrow + mi * 16 + grp;
#pragma unroll
        for (int ni = 0; ni < 8; ++ni) {
            int col = ncol + ni * 8 + tg * 2;
            float2 bb = *(const float2*)&b2[col];
            if (r0 < N_NODES)
                *(float2*)&out[(size_t)r0 * HID + col] =
                    make_float2(acc[mi][ni][0] + bb.x, acc[mi][ni][1] + bb.y);
            if (r0 + 8 < N_NODES)
                *(float2*)&out[(size_t)(r0 + 8) * HID + col] =
                    make_float2(acc[mi][ni][2] + bb.x, acc[mi][ni][3] + bb.y);
        }
    }
}

// ---------------- launch ----------------
extern "C" void kernel_launch(void* const* d_in, const int* in_sizes, int n_in,
                              void* d_out, int out_size) {
    const void* edge_index = d_in[0];
    const void* edge_type = d_in[1];
    const float* node_emb = (const float*)d_in[2];
    const float* W1 = (const float*)d_in[3];
    const float* root1 = (const float*)d_in[4];
    const float* b1 = (const float*)d_in[5];
    const float* W2 = (const float*)d_in[6];
    const float* root2 = (const float*)d_in[7];
    const float* b2 = (const float*)d_in[8];
    float* out = (float*)d_out;

    static int attr_done = 0;
    if (!attr_done) {
        cudaFuncSetAttribute(k_l1, cudaFuncAttributeMaxDynamicSharedMemorySize, L1_SMEM);
        cudaFuncSetAttribute(k_l2t, cudaFuncAttributeMaxDynamicSharedMemorySize, L2T_SMEM);
        attr_done = 1;
    }

    k_detect<<<1, 32>>>((const int*)edge_index, (const int*)edge_type);

    k_init<<<640, 1024>>>();
    k_count<<<1172, 256>>>(edge_index, edge_type);
    k_scan1<<<SCAN_BLOCKS, 1024>>>();
    k_scan2<<<1, 1024>>>();
    k_scan3<<<640, 1024>>>();
    k_bucket<<<1172, 256>>>(edge_index, edge_type);
    k_wsplit<<<33, 256>>>(W2, root2);

    k_l1<<<625, 256, L1_SMEM>>>(node_emb, W1, root1, b1);
    k_l2t<<<157, 256, L2T_SMEM>>>(b2, out);
}

// round 14
// speedup vs baseline: 2.6761x; 1.2616x over previous
#include <cuda_runtime.h>
#include <cuda_bf16.h>
#include <cstdint>

#define N_NODES 20000
#define N_REL 32
#define HID 128
#define EMBD 16
#define N_EDGES 600000
#define NSEG (N_NODES * N_REL)    // 640000
#define SCAN_BLOCKS (NSEG / 1024) // 625 exactly

// ---------------- scratch (device globals, 16B-aligned; ~28 MB) ----------------
__device__ __align__(16) int   g_scnt[NSEG];
__device__ __align__(16) int   g_tmp[NSEG];
__device__ __align__(16) int   g_rowptr[NSEG + 1];
__device__ __align__(16) int   g_cursor[NSEG];
__device__ __align__(16) float g_inv[NSEG];
__device__ __align__(16) int   g_esrc[N_EDGES];     // (rel<<16)|src per edge, bucketed by segment
__device__ __align__(16) float g_h1[N_NODES * HID];
__device__ __align__(16) int   g_bsum[SCAN_BLOCKS];
__device__ __align__(16) int   g_bexcl[SCAN_BLOCKS];
// split-bf16 layer-2 weights, natural row-major [k][n]: 33 rels x [128][128]
__device__ __align__(16) __nv_bfloat16 g_wt_hi[33 * 128 * 128];
__device__ __align__(16) __nv_bfloat16 g_wt_lo[33 * 128 * 128];
__device__ int g_ei64;
__device__ int g_et64;

__device__ __forceinline__ int load_idx(const void* p, long long i, int is64) {
    return is64 ? (int)((const long long*)p)[i] : ((const int*)p)[i];
}

__device__ __forceinline__ uint32_t smem_u32(const void* p) {
    uint32_t a;
    asm("{ .reg .u64 t; cvta.to.shared.u64 t, %1; cvt.u32.u64 %0, t; }" : "=r"(a) : "l"(p));
    return a;
}

__device__ __forceinline__ uint32_t pack_bf2(float x, float y) {
    __nv_bfloat162 h = __floats2bfloat162_rn(x, y);
    return *(uint32_t*)&h;
}

__device__ __forceinline__ void ldsm_x4(uint32_t& r0, uint32_t& r1, uint32_t& r2, uint32_t& r3,
                                        uint32_t addr) {
    asm volatile("ldmatrix.sync.aligned.m8n8.x4.shared.b16 {%0,%1,%2,%3}, [%4];"
                 : "=r"(r0), "=r"(r1), "=r"(r2), "=r"(r3) : "r"(addr));
}
__device__ __forceinline__ void ldsm_x4_t(uint32_t& r0, uint32_t& r1, uint32_t& r2, uint32_t& r3,
                                          uint32_t addr) {
    asm volatile("ldmatrix.sync.aligned.m8n8.x4.trans.shared.b16 {%0,%1,%2,%3}, [%4];"
                 : "=r"(r0), "=r"(r1), "=r"(r2), "=r"(r3) : "r"(addr));
}
__device__ __forceinline__ void mma16816(float* c, uint32_t a0, uint32_t a1, uint32_t a2,
                                         uint32_t a3, uint32_t b0, uint32_t b1) {
    asm volatile(
        "mma.sync.aligned.m16n8k16.row.col.f32.bf16.bf16.f32 "
        "{%0,%1,%2,%3}, {%4,%5,%6,%7}, {%8,%9}, {%0,%1,%2,%3};"
        : "+f"(c[0]), "+f"(c[1]), "+f"(c[2]), "+f"(c[3])
        : "r"(a0), "r"(a1), "r"(a2), "r"(a3), "r"(b0), "r"(b1));
}

// ---------------- dtype detection (int32 vs int64 index arrays) ----------------
__global__ void k_detect(const int* __restrict__ ei, const int* __restrict__ et) {
    if (blockIdx.x == 0 && threadIdx.x == 0) {
        int a = 1, b = 1;
        for (int i = 0; i < 64; i++) if (ei[2 * i + 1] != 0) { a = 0; break; }
        for (int i = 0; i < 64; i++) if (et[2 * i + 1] != 0) { b = 0; break; }
        g_ei64 = a;
        g_et64 = b;
    }
}

// ---------------- preprocessing ----------------
__global__ void k_init() {
    int i0 = blockIdx.x * blockDim.x + threadIdx.x;
    int stride = gridDim.x * blockDim.x;
    for (int i = i0; i < NSEG; i += stride) g_scnt[i] = 0;
}

__global__ void k_count(const void* __restrict__ ei, const void* __restrict__ et) {
    int i0 = blockIdx.x * blockDim.x + threadIdx.x;
    int stride = gridDim.x * blockDim.x;
    int e64 = g_ei64, t64 = g_et64;
    for (int e = i0; e < N_EDGES; e += stride) {
        int dst = load_idx(ei, (long long)N_EDGES + e, e64);
        int r = load_idx(et, e, t64);
        if ((unsigned)dst >= N_NODES || (unsigned)r >= N_REL) continue;
        atomicAdd(&g_scnt[dst * N_REL + r], 1);
    }
}

__global__ void k_scan1() {
    __shared__ int sdata[1024];
    int tid = threadIdx.x;
    int i = blockIdx.x * 1024 + tid;
    int v = g_scnt[i];
    g_inv[i] = (v > 0) ? (1.0f / (float)v) : 0.0f;
    sdata[tid] = v;
    __syncthreads();
    for (int off = 1; off < 1024; off <<= 1) {
        int tmp = (tid >= off) ? sdata[tid - off] : 0;
        __syncthreads();
        sdata[tid] += tmp;
        __syncthreads();
    }
    g_tmp[i] = sdata[tid];
    if (tid == 1023) g_bsum[blockIdx.x] = sdata[1023];
}

__global__ void k_scan2() {
    __shared__ int sdata[1024];
    int tid = threadIdx.x;
    int v = (tid < SCAN_BLOCKS) ? g_bsum[tid] : 0;
    sdata[tid] = v;
    __syncthreads();
    for (int off = 1; off < 1024; off <<= 1) {
        int tmp = (tid >= off) ? sdata[tid - off] : 0;
        __syncthreads();
        sdata[tid] += tmp;
        __syncthreads();
    }
    if (tid < SCAN_BLOCKS) g_bexcl[tid] = sdata[tid] - v;
}

__global__ void k_scan3() {
    int i0 = blockIdx.x * blockDim.x + threadIdx.x;
    int stride = gridDim.x * blockDim.x;
    for (int i = i0; i < NSEG; i += stride) {
        int val = g_bexcl[i >> 10] + g_tmp[i];
        g_rowptr[i + 1] = val;
        g_cursor[i] = val - g_scnt[i];
    }
    if (i0 == 0) g_rowptr[0] = 0;
}

__global__ void k_bucket(const void* __restrict__ ei, const void* __restrict__ et) {
    int i0 = blockIdx.x * blockDim.x + threadIdx.x;
    int stride = gridDim.x * blockDim.x;
    int e64 = g_ei64, t64 = g_et64;
    for (int e = i0; e < N_EDGES; e += stride) {
        int src = load_idx(ei, e, e64);
        int dst = load_idx(ei, (long long)N_EDGES + e, e64);
        int r = load_idx(et, e, t64);
        if ((unsigned)src >= N_NODES || (unsigned)dst >= N_NODES || (unsigned)r >= N_REL) continue;
        int idx = atomicAdd(&g_cursor[dst * N_REL + r], 1);
        g_esrc[idx] = (r << 16) | src;
    }
}

// ---------------- precompute: split layer-2 weights to bf16 hi/lo, row-major [k][n] ----------
__global__ void k_wsplit(const float* __restrict__ W2, const float* __restrict__ root2) {
    int rel = blockIdx.x;
    const float* W = (rel < N_REL) ? (W2 + (size_t)rel * HID * HID) : root2;
    __nv_bfloat16* oh = g_wt_hi + (size_t)rel * HID * HID;
    __nv_bfloat16* ol = g_wt_lo + (size_t)rel * HID * HID;
    int t = threadIdx.x;
    for (int u = t; u < 2048; u += 256) {  // 2048 units of 8 contiguous values
        int base = u * 8;
        float4 w0 = *(const float4*)&W[base];
        float4 w1 = *(const float4*)&W[base + 4];
        float v[8] = {w0.x, w0.y, w0.z, w0.w, w1.x, w1.y, w1.z, w1.w};
        float l[8];
#pragma unroll
        for (int i = 0; i < 8; i++) {
            float h = __bfloat162float(__float2bfloat16_rn(v[i]));
            l[i] = v[i] - h;
        }
        *(uint4*)&oh[base] = make_uint4(pack_bf2(v[0], v[1]), pack_bf2(v[2], v[3]),
                                        pack_bf2(v[4], v[5]), pack_bf2(v[6], v[7]));
        *(uint4*)&ol[base] = make_uint4(pack_bf2(l[0], l[1]), pack_bf2(l[2], l[3]),
                                        pack_bf2(l[4], l[5]), pack_bf2(l[6], l[7]));
    }
}

// ==================== layer 1 (fp32 SIMT, unchanged — protected win) ====================
#define L1_AS 548
#define L1_SMEM ((32 * L1_AS + 32 * 132) * 4)

__global__ void __launch_bounds__(256) k_l1(const float* __restrict__ emb,
                                            const float* __restrict__ W1,
                                            const float* __restrict__ root1,
                                            const float* __restrict__ b1) {
    extern __shared__ float sm[];
    float* As = sm;
    float* Bs = sm + 32 * L1_AS;
    int n0 = blockIdx.x * 32;
    int t = threadIdx.x;
    int d = t >> 3, sub = t & 7, f0 = sub * 2;

    float4 z4 = make_float4(0.f, 0.f, 0.f, 0.f);
#pragma unroll
    for (int q = 0; q < 16; ++q)
        *(float4*)&As[d * L1_AS + sub * 64 + q * 4] = z4;
    __syncthreads();

    int base = (n0 + d) * N_REL;
    int s = g_rowptr[base], e = g_rowptr[base + N_REL];
    for (int j = s; j < e; ++j) {
        int p = g_esrc[j];
        int src = p & 0xFFFF, rel = p >> 16;
        float2 v = *(const float2*)&emb[src * EMBD + f0];
        As[d * L1_AS + rel * 16 + f0]     += v.x;
        As[d * L1_AS + rel * 16 + f0 + 1] += v.y;
    }
#pragma unroll 8
    for (int rel = 0; rel < N_REL; ++rel) {
        float iv = g_inv[base + rel];
        As[d * L1_AS + rel * 16 + f0]     *= iv;
        As[d * L1_AS + rel * 16 + f0 + 1] *= iv;
    }
    {
        float2 rv = *(const float2*)&emb[(n0 + d) * EMBD + f0];
        As[d * L1_AS + 512 + f0]     = rv.x;
        As[d * L1_AS + 512 + f0 + 1] = rv.y;
    }

    int d0 = (t >> 5) * 4;
    int col0 = (t & 31) * 4;
    float acc[4][4];
#pragma unroll
    for (int i = 0; i < 4; i++)
#pragma unroll
        for (int j = 0; j < 4; j++) acc[i][j] = 0.f;

    for (int kc = 0; kc <= 16; ++kc) {
        int krows = (kc < 16) ? 32 : 16;
        const float* Bsrc = (kc < 16) ? (W1 + (size_t)(kc * 32) * HID) : root1;
        __syncthreads();
        {
            int row = t >> 3, c0f = (t & 7) * 16;
            if (row < krows) {
#pragma unroll
                for (int q = 0; q < 4; ++q)
                    *(float4*)&Bs[row * 132 + c0f + q * 4] =
                        *(const float4*)&Bsrc[(size_t)row * HID + c0f + q * 4];
            }
        }
        __syncthreads();
        int kbase = kc * 32;
        int nk4 = krows >> 2;
#pragma unroll 4
        for (int k4 = 0; k4 < nk4; ++k4) {
            int kb = kbase + k4 * 4;
            float4 a0 = *(const float4*)&As[(d0 + 0) * L1_AS + kb];
            float4 a1 = *(const float4*)&As[(d0 + 1) * L1_AS + kb];
            float4 a2 = *(const float4*)&As[(d0 + 2) * L1_AS + kb];
            float4 a3 = *(const float4*)&As[(d0 + 3) * L1_AS + kb];
            int kk = k4 * 4;
            float4 b0 = *(const float4*)&Bs[(kk + 0) * 132 + col0];
            float4 b1v = *(const float4*)&Bs[(kk + 1) * 132 + col0];
            float4 b2v = *(const float4*)&Bs[(kk + 2) * 132 + col0];
            float4 b3v = *(const float4*)&Bs[(kk + 3) * 132 + col0];
#define L1ROW(i, av)                                                                   \
            acc[i][0] += av.x * b0.x;  acc[i][1] += av.x * b0.y;                       \
            acc[i][2] += av.x * b0.z;  acc[i][3] += av.x * b0.w;                       \
            acc[i][0] += av.y * b1v.x; acc[i][1] += av.y * b1v.y;                      \
            acc[i][2] += av.y * b1v.z; acc[i][3] += av.y * b1v.w;                      \
            acc[i][0] += av.z * b2v.x; acc[i][1] += av.z * b2v.y;                      \
            acc[i][2] += av.z * b2v.z; acc[i][3] += av.z * b2v.w;                      \
            acc[i][0] += av.w * b3v.x; acc[i][1] += av.w * b3v.y;                      \
            acc[i][2] += av.w * b3v.z; acc[i][3] += av.w * b3v.w;
            L1ROW(0, a0) L1ROW(1, a1) L1ROW(2, a2) L1ROW(3, a3)
#undef L1ROW
        }
    }

    float4 bb = *(const float4*)&b1[col0];
#pragma unroll
    for (int i = 0; i < 4; ++i) {
        int n = n0 + d0 + i;
        float4 v = make_float4(fmaxf(acc[i][0] + bb.x, 0.f), fmaxf(acc[i][1] + bb.y, 0.f),
                               fmaxf(acc[i][2] + bb.z, 0.f), fmaxf(acc[i][3] + bb.w, 0.f));
        *(float4*)&g_h1[(size_t)n * HID + col0] = v;
    }
}

// ==================== layer 2: warp-specialized mma.sync bf16-split GEMM ====================
// Block = 128 dst x 128 cols, 512 threads. Warps 0-7 = consumers (B copy + mma),
// warps 8-15 = producers (gather A(rel+1) into ping-pong buffer). Per relation the
// exposed time is max(gather, mma) instead of their sum. One __syncthreads per rel.
#define L2_STRIDE 136
#define L2_TILE (128 * L2_STRIDE * 2)   // 34816 bytes per bf16 tile
// smem: Abuf[b]: hi at b*2T, lo at b*2T+T (b=0,1); B hi at 4T, lo at 5T
#define SM_BHI (4 * L2_TILE)
#define SM_BLO (5 * L2_TILE)
#define L2T_SMEM (6 * L2_TILE)          // 208896 bytes

// B copy by 256 consumer threads (ct = 0..255)
__device__ __forceinline__ void l2_copy_b(char* smc, int rel, int ct) {
    const uint4* sh = (const uint4*)(g_wt_hi + (size_t)rel * HID * HID);
    const uint4* sl = (const uint4*)(g_wt_lo + (size_t)rel * HID * HID);
#pragma unroll
    for (int i = 0; i < 8; ++i) {
        int u = ct + i * 256;           // unit of 8 bf16
        int row = u >> 4, c8 = (u & 15) * 8;
        int doff = row * L2_STRIDE + c8;
        *(uint4*)(smc + SM_BHI + doff * 2) = sh[u];
        *(uint4*)(smc + SM_BLO + doff * 2) = sl[u];
    }
}

// A gather by 256 producer threads (pt = 0..255): 4 dsts each, 16 cols per sub
__device__ __forceinline__ void l2_gather(char* abase_hi, char* abase_lo, int rel,
                                          int n0, int dg, int sub) {
    __nv_bfloat16* sA_hi = (__nv_bfloat16*)abase_hi;
    __nv_bfloat16* sA_lo = (__nv_bfloat16*)abase_lo;
    for (int dd = 0; dd < 4; ++dd) {
        int d = dg + dd * 32;
        int n = n0 + d;
        float a[16];
#pragma unroll
        for (int i = 0; i < 16; i++) a[i] = 0.f;
        if (n < N_NODES) {
            if (rel < N_REL) {
                int seg = n * N_REL + rel;
                int s = g_rowptr[seg], e = g_rowptr[seg + 1];
                for (int j = s; j < e; ++j) {
                    int src = g_esrc[j] & 0xFFFF;
                    const float* hp = &g_h1[(size_t)src * HID + sub * 16];
                    float4 v0 = *(const float4*)(hp + 0);
                    float4 v1 = *(const float4*)(hp + 4);
                    float4 v2 = *(const float4*)(hp + 8);
                    float4 v3 = *(const float4*)(hp + 12);
                    a[0] += v0.x; a[1] += v0.y; a[2] += v0.z; a[3] += v0.w;
                    a[4] += v1.x; a[5] += v1.y; a[6] += v1.z; a[7] += v1.w;
                    a[8] += v2.x; a[9] += v2.y; a[10] += v2.z; a[11] += v2.w;
                    a[12] += v3.x; a[13] += v3.y; a[14] += v3.z; a[15] += v3.w;
                }
                float iv = g_inv[seg];
#pragma unroll
                for (int i = 0; i < 16; i++) a[i] *= iv;
            } else {  // root term
                const float* hp = &g_h1[(size_t)n * HID + sub * 16];
                float4 v0 = *(const float4*)(hp + 0);
                float4 v1 = *(const float4*)(hp + 4);
                float4 v2 = *(const float4*)(hp + 8);
                float4 v3 = *(const float4*)(hp + 12);
                a[0] = v0.x; a[1] = v0.y; a[2] = v0.z; a[3] = v0.w;
                a[4] = v1.x; a[5] = v1.y; a[6] = v1.z; a[7] = v1.w;
                a[8] = v2.x; a[9] = v2.y; a[10] = v2.z; a[11] = v2.w;
                a[12] = v3.x; a[13] = v3.y; a[14] = v3.z; a[15] = v3.w;
            }
        }
        float lo[16];
#pragma unroll
        for (int i = 0; i < 16; i++) {
            float h = __bfloat162float(__float2bfloat16_rn(a[i]));
            lo[i] = a[i] - h;
        }
        int aoff = d * L2_STRIDE + sub * 16;
#pragma unroll
        for (int q = 0; q < 2; ++q) {
            *(uint4*)&sA_hi[aoff + q * 8] =
                make_uint4(pack_bf2(a[q * 8 + 0], a[q * 8 + 1]), pack_bf2(a[q * 8 + 2], a[q * 8 + 3]),
                           pack_bf2(a[q * 8 + 4], a[q * 8 + 5]), pack_bf2(a[q * 8 + 6], a[q * 8 + 7]));
            *(uint4*)&sA_lo[aoff + q * 8] =
                make_uint4(pack_bf2(lo[q * 8 + 0], lo[q * 8 + 1]), pack_bf2(lo[q * 8 + 2], lo[q * 8 + 3]),
                           pack_bf2(lo[q * 8 + 4], lo[q * 8 + 5]), pack_bf2(lo[q * 8 + 6], lo[q * 8 + 7]));
        }
    }
}

__global__ void __launch_bounds__(512, 1) k_l2t(const float* __restrict__ b2,
                                                float* __restrict__ out) {
    extern __shared__ char smc[];
    uint32_t sb = smem_u32(smc);
    int t = threadIdx.x, wid = t >> 5, lane = t & 31;
    int n0 = blockIdx.x * 128;
    bool is_consumer = (wid < 8);

    if (is_consumer) {
        // ---- consumer: B copy + ldsm + mma ----
        int ct = t;                          // 0..255
        int mrow = (wid & 3) * 32, ncol = (wid >> 2) * 64;
        int l15 = lane & 15, lhi = (lane >> 4) << 3;
        int grp = lane >> 2, tg = lane & 3;

        float acc[2][8][4];
#pragma unroll
        for (int mi = 0; mi < 2; mi++)
#pragma unroll
            for (int ni = 0; ni < 8; ni++)
#pragma unroll
                for (int q = 0; q < 4; q++) acc[mi][ni][q] = 0.f;

        __syncthreads();   // producers finished gather(0) into buf 0

        for (int rel = 0; rel <= N_REL; ++rel) {
            l2_copy_b(smc, rel, ct);
            asm volatile("bar.sync 1, 256;" ::: "memory");   // consumer-only: B ready
            uint32_t ahib = sb + (rel & 1) * 2 * L2_TILE;
            uint32_t alob = ahib + L2_TILE;
            uint32_t bhib = sb + SM_BHI, blob = sb + SM_BLO;
#pragma unroll
            for (int ks = 0; ks < 8; ++ks) {
                int k0 = ks * 16;
                uint32_t ah[2][4], al[2][4];
#pragma unroll
                for (int mi = 0; mi < 2; ++mi) {
                    uint32_t rowoff = ((mrow + mi * 16 + l15) * L2_STRIDE + k0 + lhi) * 2;
                    ldsm_x4(ah[mi][0], ah[mi][1], ah[mi][2], ah[mi][3], ahib + rowoff);
                    ldsm_x4(al[mi][0], al[mi][1], al[mi][2], al[mi][3], alob + rowoff);
                }
#pragma unroll
                for (int np = 0; np < 4; ++np) {
                    uint32_t boff = ((k0 + l15) * L2_STRIDE + ncol + np * 16 + lhi) * 2;
                    uint32_t bh0, bh1, bh2, bh3;
                    ldsm_x4_t(bh0, bh1, bh2, bh3, bhib + boff);
#pragma unroll
                    for (int mi = 0; mi < 2; ++mi) {
                        mma16816(acc[mi][np * 2 + 0], ah[mi][0], ah[mi][1], ah[mi][2], ah[mi][3], bh0, bh1);
                        mma16816(acc[mi][np * 2 + 1], ah[mi][0], ah[mi][1], ah[mi][2], ah[mi][3], bh2, bh3);
                        mma16816(acc[mi][np * 2 + 0], al[mi][0], al[mi][1], al[mi][2], al[mi][3], bh0, bh1);
                        mma16816(acc[mi][np * 2 + 1], al[mi][0], al[mi][1], al[mi][2], al[mi][3], bh2, bh3);
                    }
                    uint32_t bl0, bl1, bl2, bl3;
                    ldsm_x4_t(bl0, bl1, bl2, bl3, blob + boff);
#pragma unroll
                    for (int mi = 0; mi < 2; ++mi) {
                        mma16816(acc[mi][np * 2 + 0], ah[mi][0], ah[mi][1], ah[mi][2], ah[mi][3], bl0, bl1);
                        mma16816(acc[mi][np * 2 + 1], ah[mi][0], ah[mi][1], ah[mi][2], ah[mi][3], bl2, bl3);
                    }
                }
            }
            __syncthreads();   // mma(rel) done everywhere; gather(rel+1) complete
        }

        // ---- epilogue: + b2 -> out ----
#pragma unroll
        for (int mi = 0; mi < 2; ++mi) {
            int r0 = n0 + mrow + mi * 16 + grp;
#pragma unroll
            for (int ni = 0; ni < 8; ++ni) {
                int col = ncol + ni * 8 + tg * 2;
                float2 bb = *(const float2*)&b2[col];
                if (r0 < N_NODES)
                    *(float2*)&out[(size_t)r0 * HID + col] =
                        make_float2(acc[mi][ni][0] + bb.x, acc[mi][ni][1] + bb.y);
                if (r0 + 8 < N_NODES)
                    *(float2*)&out[(size_t)(r0 + 8) * HID + col] =
                        make_float2(acc[mi][ni][2] + bb.x, acc[mi][ni][3] + bb.y);
            }
        }
    } else {
        // ---- producer: gather A(rel+1) while consumers mma(rel) ----
        int pt = t - 256;                    // 0..255
        int dg = pt >> 3, sub = pt & 7;

        // prologue: gather(0) into buffer 0
        l2_gather(smc + 0, smc + L2_TILE, 0, n0, dg, sub);
        __syncthreads();

        for (int rel = 0; rel <= N_REL; ++rel) {
            if (rel < N_REL) {
                int nb = (rel + 1) & 1;
                l2_gather(smc + nb * 2 * L2_TILE, smc + nb * 2 * L2_TILE + L2_TILE,
                          rel + 1, n0, dg, sub);
            }
            __syncthreads();
        }
    }
}

// ---------------- launch ----------------
extern "C" void kernel_launch(void* const* d_in, const int* in_sizes, int n_in,
                              void* d_out, int out_size) {
    const void* edge_index = d_in[0];
    const void* edge_type = d_in[1];
    const float* node_emb = (const float*)d_in[2];
    const float* W1 = (const float*)d_in[3];
    const float* root1 = (const float*)d_in[4];
    const float* b1 = (const float*)d_in[5];
    const float* W2 = (const float*)d_in[6];
    const float* root2 = (const float*)d_in[7];
    const float* b2 = (const float*)d_in[8];
    float* out = (float*)d_out;

    static int attr_done = 0;
    if (!attr_done) {
        cudaFuncSetAttribute(k_l1, cudaFuncAttributeMaxDynamicSharedMemorySize, L1_SMEM);
        cudaFuncSetAttribute(k_l2t, cudaFuncAttributeMaxDynamicSharedMemorySize, L2T_SMEM);
        attr_done = 1;
    }

    k_detect<<<1, 32>>>((const int*)edge_index, (const int*)edge_type);

    k_init<<<640, 1024>>>();
    k_count<<<1172, 256>>>(edge_index, edge_type);
    k_scan1<<<SCAN_BLOCKS, 1024>>>();
    k_scan2<<<1, 1024>>>();
    k_scan3<<<640, 1024>>>();
    k_bucket<<<1172, 256>>>(edge_index, edge_type);
    k_wsplit<<<33, 256>>>(W2, root2);

    k_l1<<<625, 256, L1_SMEM>>>(node_emb, W1, root1, b1);
    k_l2t<<<157, 512, L2T_SMEM>>>(b2, out);   // 512 threads: 8 consumer + 8 producer warps
}

// round 15
// speedup vs baseline: 2.7732x; 1.0363x over previous
#include <cuda_runtime.h>
#include <cuda_bf16.h>
#include <cstdint>

#define N_NODES 20000
#define N_REL 32
#define HID 128
#define EMBD 16
#define N_EDGES 600000
#define NSEG (N_NODES * N_REL)    // 640000
#define SCAN_BLOCKS (NSEG / 1024) // 625 exactly

// ---------------- scratch (device globals, 16B-aligned; ~28 MB) ----------------
__device__ __align__(16) int   g_scnt[NSEG];
__device__ __align__(16) int   g_tmp[NSEG];
__device__ __align__(16) int   g_rowptr[NSEG + 1];
__device__ __align__(16) int   g_cursor[NSEG];
__device__ __align__(16) float g_inv[NSEG];
__device__ __align__(16) int   g_esrc[N_EDGES];     // (rel<<16)|src per edge, bucketed by segment
__device__ __align__(16) float g_h1[N_NODES * HID];
__device__ __align__(16) int   g_bsum[SCAN_BLOCKS];
__device__ __align__(16) int   g_bexcl[SCAN_BLOCKS];
// split-bf16 layer-2 weights, natural row-major [k][n]: 33 rels x [128][128]
__device__ __align__(16) __nv_bfloat16 g_wt_hi[33 * 128 * 128];
__device__ __align__(16) __nv_bfloat16 g_wt_lo[33 * 128 * 128];
__device__ int g_ei64;
__device__ int g_et64;

__device__ __forceinline__ int load_idx(const void* p, long long i, int is64) {
    return is64 ? (int)((const long long*)p)[i] : ((const int*)p)[i];
}

__device__ __forceinline__ uint32_t smem_u32(const void* p) {
    uint32_t a;
    asm("{ .reg .u64 t; cvta.to.shared.u64 t, %1; cvt.u32.u64 %0, t; }" : "=r"(a) : "l"(p));
    return a;
}

__device__ __forceinline__ uint32_t pack_bf2(float x, float y) {
    __nv_bfloat162 h = __floats2bfloat162_rn(x, y);
    return *(uint32_t*)&h;
}

__device__ __forceinline__ void ldsm_x4(uint32_t& r0, uint32_t& r1, uint32_t& r2, uint32_t& r3,
                                        uint32_t addr) {
    asm volatile("ldmatrix.sync.aligned.m8n8.x4.shared.b16 {%0,%1,%2,%3}, [%4];"
                 : "=r"(r0), "=r"(r1), "=r"(r2), "=r"(r3) : "r"(addr));
}
__device__ __forceinline__ void ldsm_x4_t(uint32_t& r0, uint32_t& r1, uint32_t& r2, uint32_t& r3,
                                          uint32_t addr) {
    asm volatile("ldmatrix.sync.aligned.m8n8.x4.trans.shared.b16 {%0,%1,%2,%3}, [%4];"
                 : "=r"(r0), "=r"(r1), "=r"(r2), "=r"(r3) : "r"(addr));
}
__device__ __forceinline__ void mma16816(float* c, uint32_t a0, uint32_t a1, uint32_t a2,
                                         uint32_t a3, uint32_t b0, uint32_t b1) {
    asm volatile(
        "mma.sync.aligned.m16n8k16.row.col.f32.bf16.bf16.f32 "
        "{%0,%1,%2,%3}, {%4,%5,%6,%7}, {%8,%9}, {%0,%1,%2,%3};"
        : "+f"(c[0]), "+f"(c[1]), "+f"(c[2]), "+f"(c[3])
        : "r"(a0), "r"(a1), "r"(a2), "r"(a3), "r"(b0), "r"(b1));
}

// ---------------- dtype detection (int32 vs int64 index arrays) ----------------
__global__ void k_detect(const int* __restrict__ ei, const int* __restrict__ et) {
    if (blockIdx.x == 0 && threadIdx.x == 0) {
        int a = 1, b = 1;
        for (int i = 0; i < 64; i++) if (ei[2 * i + 1] != 0) { a = 0; break; }
        for (int i = 0; i < 64; i++) if (et[2 * i + 1] != 0) { b = 0; break; }
        g_ei64 = a;
        g_et64 = b;
    }
}

// ---------------- preprocessing ----------------
__global__ void k_init() {
    int i0 = blockIdx.x * blockDim.x + threadIdx.x;
    int stride = gridDim.x * blockDim.x;
    for (int i = i0; i < NSEG; i += stride) g_scnt[i] = 0;
}

__global__ void k_count(const void* __restrict__ ei, const void* __restrict__ et) {
    int i0 = blockIdx.x * blockDim.x + threadIdx.x;
    int stride = gridDim.x * blockDim.x;
    int e64 = g_ei64, t64 = g_et64;
    for (int e = i0; e < N_EDGES; e += stride) {
        int dst = load_idx(ei, (long long)N_EDGES + e, e64);
        int r = load_idx(et, e, t64);
        if ((unsigned)dst >= N_NODES || (unsigned)r >= N_REL) continue;
        atomicAdd(&g_scnt[dst * N_REL + r], 1);
    }
}

__global__ void k_scan1() {
    __shared__ int sdata[1024];
    int tid = threadIdx.x;
    int i = blockIdx.x * 1024 + tid;
    int v = g_scnt[i];
    g_inv[i] = (v > 0) ? (1.0f / (float)v) : 0.0f;
    sdata[tid] = v;
    __syncthreads();
    for (int off = 1; off < 1024; off <<= 1) {
        int tmp = (tid >= off) ? sdata[tid - off] : 0;
        __syncthreads();
        sdata[tid] += tmp;
        __syncthreads();
    }
    g_tmp[i] = sdata[tid];
    if (tid == 1023) g_bsum[blockIdx.x] = sdata[1023];
}

__global__ void k_scan2() {
    __shared__ int sdata[1024];
    int tid = threadIdx.x;
    int v = (tid < SCAN_BLOCKS) ? g_bsum[tid] : 0;
    sdata[tid] = v;
    __syncthreads();
    for (int off = 1; off < 1024; off <<= 1) {
        int tmp = (tid >= off) ? sdata[tid - off] : 0;
        __syncthreads();
        sdata[tid] += tmp;
        __syncthreads();
    }
    if (tid < SCAN_BLOCKS) g_bexcl[tid] = sdata[tid] - v;
}

__global__ void k_scan3() {
    int i0 = blockIdx.x * blockDim.x + threadIdx.x;
    int stride = gridDim.x * blockDim.x;
    for (int i = i0; i < NSEG; i += stride) {
        int val = g_bexcl[i >> 10] + g_tmp[i];
        g_rowptr[i + 1] = val;
        g_cursor[i] = val - g_scnt[i];
    }
    if (i0 == 0) g_rowptr[0] = 0;
}

__global__ void k_bucket(const void* __restrict__ ei, const void* __restrict__ et) {
    int i0 = blockIdx.x * blockDim.x + threadIdx.x;
    int stride = gridDim.x * blockDim.x;
    int e64 = g_ei64, t64 = g_et64;
    for (int e = i0; e < N_EDGES; e += stride) {
        int src = load_idx(ei, e, e64);
        int dst = load_idx(ei, (long long)N_EDGES + e, e64);
        int r = load_idx(et, e, t64);
        if ((unsigned)src >= N_NODES || (unsigned)dst >= N_NODES || (unsigned)r >= N_REL) continue;
        int idx = atomicAdd(&g_cursor[dst * N_REL + r], 1);
        g_esrc[idx] = (r << 16) | src;
    }
}

// ---------------- precompute: split layer-2 weights to bf16 hi/lo, row-major [k][n] ----------
__global__ void k_wsplit(const float* __restrict__ W2, const float* __restrict__ root2) {
    int rel = blockIdx.x;
    const float* W = (rel < N_REL) ? (W2 + (size_t)rel * HID * HID) : root2;
    __nv_bfloat16* oh = g_wt_hi + (size_t)rel * HID * HID;
    __nv_bfloat16* ol = g_wt_lo + (size_t)rel * HID * HID;
    int t = threadIdx.x;
    for (int u = t; u < 2048; u += 256) {  // 2048 units of 8 contiguous values
        int base = u * 8;
        float4 w0 = *(const float4*)&W[base];
        float4 w1 = *(const float4*)&W[base + 4];
        float v[8] = {w0.x, w0.y, w0.z, w0.w, w1.x, w1.y, w1.z, w1.w};
        float l[8];
#pragma unroll
        for (int i = 0; i < 8; i++) {
            float h = __bfloat162float(__float2bfloat16_rn(v[i]));
            l[i] = v[i] - h;
        }
        *(uint4*)&oh[base] = make_uint4(pack_bf2(v[0], v[1]), pack_bf2(v[2], v[3]),
                                        pack_bf2(v[4], v[5]), pack_bf2(v[6], v[7]));
        *(uint4*)&ol[base] = make_uint4(pack_bf2(l[0], l[1]), pack_bf2(l[2], l[3]),
                                        pack_bf2(l[4], l[5]), pack_bf2(l[6], l[7]));
    }
}

// ==================== layer 1 (fp32 SIMT, unchanged — protected win) ====================
#define L1_AS 548
#define L1_SMEM ((32 * L1_AS + 32 * 132) * 4)

__global__ void __launch_bounds__(256) k_l1(const float* __restrict__ emb,
                                            const float* __restrict__ W1,
                                            const float* __restrict__ root1,
                                            const float* __restrict__ b1) {
    extern __shared__ float sm[];
    float* As = sm;
    float* Bs = sm + 32 * L1_AS;
    int n0 = blockIdx.x * 32;
    int t = threadIdx.x;
    int d = t >> 3, sub = t & 7, f0 = sub * 2;

    float4 z4 = make_float4(0.f, 0.f, 0.f, 0.f);
#pragma unroll
    for (int q = 0; q < 16; ++q)
        *(float4*)&As[d * L1_AS + sub * 64 + q * 4] = z4;
    __syncthreads();

    int base = (n0 + d) * N_REL;
    int s = g_rowptr[base], e = g_rowptr[base + N_REL];
    for (int j = s; j < e; ++j) {
        int p = g_esrc[j];
        int src = p & 0xFFFF, rel = p >> 16;
        float2 v = *(const float2*)&emb[src * EMBD + f0];
        As[d * L1_AS + rel * 16 + f0]     += v.x;
        As[d * L1_AS + rel * 16 + f0 + 1] += v.y;
    }
#pragma unroll 8
    for (int rel = 0; rel < N_REL; ++rel) {
        float iv = g_inv[base + rel];
        As[d * L1_AS + rel * 16 + f0]     *= iv;
        As[d * L1_AS + rel * 16 + f0 + 1] *= iv;
    }
    {
        float2 rv = *(const float2*)&emb[(n0 + d) * EMBD + f0];
        As[d * L1_AS + 512 + f0]     = rv.x;
        As[d * L1_AS + 512 + f0 + 1] = rv.y;
    }

    int d0 = (t >> 5) * 4;
    int col0 = (t & 31) * 4;
    float acc[4][4];
#pragma unroll
    for (int i = 0; i < 4; i++)
#pragma unroll
        for (int j = 0; j < 4; j++) acc[i][j] = 0.f;

    for (int kc = 0; kc <= 16; ++kc) {
        int krows = (kc < 16) ? 32 : 16;
        const float* Bsrc = (kc < 16) ? (W1 + (size_t)(kc * 32) * HID) : root1;
        __syncthreads();
        {
            int row = t >> 3, c0f = (t & 7) * 16;
            if (row < krows) {
#pragma unroll
                for (int q = 0; q < 4; ++q)
                    *(float4*)&Bs[row * 132 + c0f + q * 4] =
                        *(const float4*)&Bsrc[(size_t)row * HID + c0f + q * 4];
            }
        }
        __syncthreads();
        int kbase = kc * 32;
        int nk4 = krows >> 2;
#pragma unroll 4
        for (int k4 = 0; k4 < nk4; ++k4) {
            int kb = kbase + k4 * 4;
            float4 a0 = *(const float4*)&As[(d0 + 0) * L1_AS + kb];
            float4 a1 = *(const float4*)&As[(d0 + 1) * L1_AS + kb];
            float4 a2 = *(const float4*)&As[(d0 + 2) * L1_AS + kb];
            float4 a3 = *(const float4*)&As[(d0 + 3) * L1_AS + kb];
            int kk = k4 * 4;
            float4 b0 = *(const float4*)&Bs[(kk + 0) * 132 + col0];
            float4 b1v = *(const float4*)&Bs[(kk + 1) * 132 + col0];
            float4 b2v = *(const float4*)&Bs[(kk + 2) * 132 + col0];
            float4 b3v = *(const float4*)&Bs[(kk + 3) * 132 + col0];
#define L1ROW(i, av)                                                                   \
            acc[i][0] += av.x * b0.x;  acc[i][1] += av.x * b0.y;                       \
            acc[i][2] += av.x * b0.z;  acc[i][3] += av.x * b0.w;                       \
            acc[i][0] += av.y * b1v.x; acc[i][1] += av.y * b1v.y;                      \
            acc[i][2] += av.y * b1v.z; acc[i][3] += av.y * b1v.w;                      \
            acc[i][0] += av.z * b2v.x; acc[i][1] += av.z * b2v.y;                      \
            acc[i][2] += av.z * b2v.z; acc[i][3] += av.z * b2v.w;                      \
            acc[i][0] += av.w * b3v.x; acc[i][1] += av.w * b3v.y;                      \
            acc[i][2] += av.w * b3v.z; acc[i][3] += av.w * b3v.w;
            L1ROW(0, a0) L1ROW(1, a1) L1ROW(2, a2) L1ROW(3, a3)
#undef L1ROW
        }
    }

    float4 bb = *(const float4*)&b1[col0];
#pragma unroll
    for (int i = 0; i < 4; ++i) {
        int n = n0 + d0 + i;
        float4 v = make_float4(fmaxf(acc[i][0] + bb.x, 0.f), fmaxf(acc[i][1] + bb.y, 0.f),
                               fmaxf(acc[i][2] + bb.z, 0.f), fmaxf(acc[i][3] + bb.w, 0.f));
        *(float4*)&g_h1[(size_t)n * HID + col0] = v;
    }
}

// ==================== layer 2: warp-specialized mma.sync bf16-split GEMM ====================
// Block = 128 dst x 128 cols, 512 threads. Warps 0-7 = consumers (B copy + mma),
// warps 8-15 = producers (gather A(rel+1) into ping-pong buffer).
// Producer partition: 1 dst x 64 cols per thread (2 threads/dst) -> ONE pointer-chase
// chain per rel per thread (rowptr -> esrc -> 16 parallel float4 loads), vs 4 serial
// chains before.
#define L2_STRIDE 136
#define L2_TILE (128 * L2_STRIDE * 2)   // 34816 bytes per bf16 tile
// smem: Abuf[b]: hi at b*2T, lo at b*2T+T (b=0,1); B hi at 4T, lo at 5T
#define SM_BHI (4 * L2_TILE)
#define SM_BLO (5 * L2_TILE)
#define L2T_SMEM (6 * L2_TILE)          // 208896 bytes

// B copy by 256 consumer threads (ct = 0..255)
__device__ __forceinline__ void l2_copy_b(char* smc, int rel, int ct) {
    const uint4* sh = (const uint4*)(g_wt_hi + (size_t)rel * HID * HID);
    const uint4* sl = (const uint4*)(g_wt_lo + (size_t)rel * HID * HID);
#pragma unroll
    for (int i = 0; i < 8; ++i) {
        int u = ct + i * 256;           // unit of 8 bf16
        int row = u >> 4, c8 = (u & 15) * 8;
        int doff = row * L2_STRIDE + c8;
        *(uint4*)(smc + SM_BHI + doff * 2) = sh[u];
        *(uint4*)(smc + SM_BLO + doff * 2) = sl[u];
    }
}

// A gather by 256 producer threads: thread pt handles dst (pt>>1), cols (pt&1)*64..+63.
__device__ __forceinline__ void l2_gather(char* abase_hi, char* abase_lo, int rel,
                                          int n0, int pt) {
    __nv_bfloat16* sA_hi = (__nv_bfloat16*)abase_hi;
    __nv_bfloat16* sA_lo = (__nv_bfloat16*)abase_lo;
    int d = pt >> 1;
    int c0 = (pt & 1) * 64;
    int n = n0 + d;

    float a[64];
#pragma unroll
    for (int i = 0; i < 64; i++) a[i] = 0.f;

    if (n < N_NODES) {
        if (rel < N_REL) {
            int seg = n * N_REL + rel;
            int s = g_rowptr[seg], e = g_rowptr[seg + 1];
            for (int j = s; j < e; ++j) {
                int src = g_esrc[j] & 0xFFFF;
                const float4* hp = (const float4*)(g_h1 + (size_t)src * HID + c0);
#pragma unroll
                for (int q = 0; q < 16; ++q) {
                    float4 v = hp[q];
                    a[q * 4 + 0] += v.x;
                    a[q * 4 + 1] += v.y;
                    a[q * 4 + 2] += v.z;
                    a[q * 4 + 3] += v.w;
                }
            }
            float iv = g_inv[seg];
#pragma unroll
            for (int i = 0; i < 64; i++) a[i] *= iv;
        } else {  // root term: A = h1 row itself
            const float4* hp = (const float4*)(g_h1 + (size_t)n * HID + c0);
#pragma unroll
            for (int q = 0; q < 16; ++q) {
                float4 v = hp[q];
                a[q * 4 + 0] = v.x;
                a[q * 4 + 1] = v.y;
                a[q * 4 + 2] = v.z;
                a[q * 4 + 3] = v.w;
            }
        }
    }

    int aoff = d * L2_STRIDE + c0;
#pragma unroll
    for (int g = 0; g < 8; ++g) {   // 8 groups of 8 values
        float* ag = a + g * 8;
        float lo[8];
#pragma unroll
        for (int i = 0; i < 8; i++) {
            float h = __bfloat162float(__float2bfloat16_rn(ag[i]));
            lo[i] = ag[i] - h;
        }
        *(uint4*)&sA_hi[aoff + g * 8] =
            make_uint4(pack_bf2(ag[0], ag[1]), pack_bf2(ag[2], ag[3]),
                       pack_bf2(ag[4], ag[5]), pack_bf2(ag[6], ag[7]));
        *(uint4*)&sA_lo[aoff + g * 8] =
            make_uint4(pack_bf2(lo[0], lo[1]), pack_bf2(lo[2], lo[3]),
                       pack_bf2(lo[4], lo[5]), pack_bf2(lo[6], lo[7]));
    }
}

__global__ void __launch_bounds__(512, 1) k_l2t(const float* __restrict__ b2,
                                                float* __restrict__ out) {
    extern __shared__ char smc[];
    uint32_t sb = smem_u32(smc);
    int t = threadIdx.x, wid = t >> 5, lane = t & 31;
    int n0 = blockIdx.x * 128;
    bool is_consumer = (wid < 8);

    if (is_consumer) {
        // ---- consumer: B copy + ldsm + mma ----
        int ct = t;                          // 0..255
        int mrow = (wid & 3) * 32, ncol = (wid >> 2) * 64;
        int l15 = lane & 15, lhi = (lane >> 4) << 3;
        int grp = lane >> 2, tg = lane & 3;

        float acc[2][8][4];
#pragma unroll
        for (int mi = 0; mi < 2; mi++)
#pragma unroll
            for (int ni = 0; ni < 8; ni++)
#pragma unroll
                for (int q = 0; q < 4; q++) acc[mi][ni][q] = 0.f;

        __syncthreads();   // producers finished gather(0) into buf 0

        for (int rel = 0; rel <= N_REL; ++rel) {
            l2_copy_b(smc, rel, ct);
            asm volatile("bar.sync 1, 256;" ::: "memory");   // consumer-only: B ready
            uint32_t ahib = sb + (rel & 1) * 2 * L2_TILE;
            uint32_t alob = ahib + L2_TILE;
            uint32_t bhib = sb + SM_BHI, blob = sb + SM_BLO;
#pragma unroll
            for (int ks = 0; ks < 8; ++ks) {
                int k0 = ks * 16;
                uint32_t ah[2][4], al[2][4];
#pragma unroll
                for (int mi = 0; mi < 2; ++mi) {
                    uint32_t rowoff = ((mrow + mi * 16 + l15) * L2_STRIDE + k0 + lhi) * 2;
                    ldsm_x4(ah[mi][0], ah[mi][1], ah[mi][2], ah[mi][3], ahib + rowoff);
                    ldsm_x4(al[mi][0], al[mi][1], al[mi][2], al[mi][3], alob + rowoff);
                }
#pragma unroll
                for (int np = 0; np < 4; ++np) {
                    uint32_t boff = ((k0 + l15) * L2_STRIDE + ncol + np * 16 + lhi) * 2;
                    uint32_t bh0, bh1, bh2, bh3;
                    ldsm_x4_t(bh0, bh1, bh2, bh3, bhib + boff);
#pragma unroll
                    for (int mi = 0; mi < 2; ++mi) {
                        mma16816(acc[mi][np * 2 + 0], ah[mi][0], ah[mi][1], ah[mi][2], ah[mi][3], bh0, bh1);
                        mma16816(acc[mi][np * 2 + 1], ah[mi][0], ah[mi][1], ah[mi][2], ah[mi][3], bh2, bh3);
                        mma16816(acc[mi][np * 2 + 0], al[mi][0], al[mi][1], al[mi][2], al[mi][3], bh0, bh1);
                        mma16816(acc[mi][np * 2 + 1], al[mi][0], al[mi][1], al[mi][2], al[mi][3], bh2, bh3);
                    }
                    uint32_t bl0, bl1, bl2, bl3;
                    ldsm_x4_t(bl0, bl1, bl2, bl3, blob + boff);
#pragma unroll
                    for (int mi = 0; mi < 2; ++mi) {
                        mma16816(acc[mi][np * 2 + 0], ah[mi][0], ah[mi][1], ah[mi][2], ah[mi][3], bl0, bl1);
                        mma16816(acc[mi][np * 2 + 1], ah[mi][0], ah[mi][1], ah[mi][2], ah[mi][3], bl2, bl3);
                    }
                }
            }
            __syncthreads();   // mma(rel) done everywhere; gather(rel+1) complete
        }

        // ---- epilogue: + b2 -> out ----
#pragma unroll
        for (int mi = 0; mi < 2; ++mi) {
            int r0 = n0 + mrow + mi * 16 + grp;
#pragma unroll
            for (int ni = 0; ni < 8; ++ni) {
                int col = ncol + ni * 8 + tg * 2;
                float2 bb = *(const float2*)&b2[col];
                if (r0 < N_NODES)
                    *(float2*)&out[(size_t)r0 * HID + col] =
                        make_float2(acc[mi][ni][0] + bb.x, acc[mi][ni][1] + bb.y);
                if (r0 + 8 < N_NODES)
                    *(float2*)&out[(size_t)(r0 + 8) * HID + col] =
                        make_float2(acc[mi][ni][2] + bb.x, acc[mi][ni][3] + bb.y);
            }
        }
    } else {
        // ---- producer: gather A(rel+1) while consumers mma(rel) ----
        int pt = t - 256;                    // 0..255

        // prologue: gather(0) into buffer 0
        l2_gather(smc + 0, smc + L2_TILE, 0, n0, pt);
        __syncthreads();

        for (int rel = 0; rel <= N_REL; ++rel) {
            if (rel < N_REL) {
                int nb = (rel + 1) & 1;
                l2_gather(smc + nb * 2 * L2_TILE, smc + nb * 2 * L2_TILE + L2_TILE,
                          rel + 1, n0, pt);
            }
            __syncthreads();
        }
    }
}

// ---------------- launch ----------------
extern "C" void kernel_launch(void* const* d_in, const int* in_sizes, int n_in,
                              void* d_out, int out_size) {
    const void* edge_index = d_in[0];
    const void* edge_type = d_in[1];
    const float* node_emb = (const float*)d_in[2];
    const float* W1 = (const float*)d_in[3];
    const float* root1 = (const float*)d_in[4];
    const float* b1 = (const float*)d_in[5];
    const float* W2 = (const float*)d_in[6];
    const float* root2 = (const float*)d_in[7];
    const float* b2 = (const float*)d_in[8];
    float* out = (float*)d_out;

    static int attr_done = 0;
    if (!attr_done) {
        cudaFuncSetAttribute(k_l1, cudaFuncAttributeMaxDynamicSharedMemorySize, L1_SMEM);
        cudaFuncSetAttribute(k_l2t, cudaFuncAttributeMaxDynamicSharedMemorySize, L2T_SMEM);
        attr_done = 1;
    }

    k_detect<<<1, 32>>>((const int*)edge_index, (const int*)edge_type);

    k_init<<<640, 1024>>>();
    k_count<<<1172, 256>>>(edge_index, edge_type);
    k_scan1<<<SCAN_BLOCKS, 1024>>>();
    k_scan2<<<1, 1024>>>();
    k_scan3<<<640, 1024>>>();
    k_bucket<<<1172, 256>>>(edge_index, edge_type);
    k_wsplit<<<33, 256>>>(W2, root2);

    k_l1<<<625, 256, L1_SMEM>>>(node_emb, W1, root1, b1);
    k_l2t<<<157, 512, L2T_SMEM>>>(b2, out);   // 512 threads: 8 consumer + 8 producer warps
}

// round 16
// speedup vs baseline: 3.0966x; 1.1166x over previous
#include <cuda_runtime.h>
#include <cuda_bf16.h>
#include <cuda_fp16.h>
#include <cstdint>

#define N_NODES 20000
#define N_REL 32
#define HID 128
#define EMBD 16
#define N_EDGES 600000
#define NSEG (N_NODES * N_REL)    // 640000
#define SCAN_BLOCKS (NSEG / 1024) // 625 exactly

// ---------------- scratch (device globals, 16B-aligned; ~26 MB) ----------------
__device__ __align__(16) int   g_scnt[NSEG];
__device__ __align__(16) int   g_tmp[NSEG];
__device__ __align__(16) int   g_rowptr[NSEG + 1];
__device__ __align__(16) int   g_cursor[NSEG];
__device__ __align__(16) float g_inv[NSEG];
__device__ __align__(16) int   g_esrc[N_EDGES];     // (rel<<16)|src per edge, bucketed by segment
__device__ __align__(16) float g_h1[N_NODES * HID];
__device__ __align__(16) int   g_bsum[SCAN_BLOCKS];
__device__ __align__(16) int   g_bexcl[SCAN_BLOCKS];
// fp16 layer-2 weights, natural row-major [k][n]: 33 rels x [128][128]
__device__ __align__(16) __half g_wt[33 * 128 * 128];
__device__ int g_ei64;
__device__ int g_et64;

__device__ __forceinline__ int load_idx(const void* p, long long i, int is64) {
    return is64 ? (int)((const long long*)p)[i] : ((const int*)p)[i];
}

__device__ __forceinline__ uint32_t smem_u32(const void* p) {
    uint32_t a;
    asm("{ .reg .u64 t; cvta.to.shared.u64 t, %1; cvt.u32.u64 %0, t; }" : "=r"(a) : "l"(p));
    return a;
}

__device__ __forceinline__ uint32_t pack_h2(float x, float y) {
    __half2 h = __floats2half2_rn(x, y);
    return *(uint32_t*)&h;
}

__device__ __forceinline__ void ldsm_x4(uint32_t& r0, uint32_t& r1, uint32_t& r2, uint32_t& r3,
                                        uint32_t addr) {
    asm volatile("ldmatrix.sync.aligned.m8n8.x4.shared.b16 {%0,%1,%2,%3}, [%4];"
                 : "=r"(r0), "=r"(r1), "=r"(r2), "=r"(r3) : "r"(addr));
}
__device__ __forceinline__ void ldsm_x4_t(uint32_t& r0, uint32_t& r1, uint32_t& r2, uint32_t& r3,
                                          uint32_t addr) {
    asm volatile("ldmatrix.sync.aligned.m8n8.x4.trans.shared.b16 {%0,%1,%2,%3}, [%4];"
                 : "=r"(r0), "=r"(r1), "=r"(r2), "=r"(r3) : "r"(addr));
}
__device__ __forceinline__ void mma16816(float* c, uint32_t a0, uint32_t a1, uint32_t a2,
                                         uint32_t a3, uint32_t b0, uint32_t b1) {
    asm volatile(
        "mma.sync.aligned.m16n8k16.row.col.f32.f16.f16.f32 "
        "{%0,%1,%2,%3}, {%4,%5,%6,%7}, {%8,%9}, {%0,%1,%2,%3};"
        : "+f"(c[0]), "+f"(c[1]), "+f"(c[2]), "+f"(c[3])
        : "r"(a0), "r"(a1), "r"(a2), "r"(a3), "r"(b0), "r"(b1));
}

// ---------------- dtype detection (int32 vs int64 index arrays) ----------------
__global__ void k_detect(const int* __restrict__ ei, const int* __restrict__ et) {
    if (blockIdx.x == 0 && threadIdx.x == 0) {
        int a = 1, b = 1;
        for (int i = 0; i < 64; i++) if (ei[2 * i + 1] != 0) { a = 0; break; }
        for (int i = 0; i < 64; i++) if (et[2 * i + 1] != 0) { b = 0; break; }
        g_ei64 = a;
        g_et64 = b;
    }
}

// ---------------- preprocessing ----------------
__global__ void k_init() {
    int i0 = blockIdx.x * blockDim.x + threadIdx.x;
    int stride = gridDim.x * blockDim.x;
    for (int i = i0; i < NSEG; i += stride) g_scnt[i] = 0;
}

__global__ void k_count(const void* __restrict__ ei, const void* __restrict__ et) {
    int i0 = blockIdx.x * blockDim.x + threadIdx.x;
    int stride = gridDim.x * blockDim.x;
    int e64 = g_ei64, t64 = g_et64;
    for (int e = i0; e < N_EDGES; e += stride) {
        int dst = load_idx(ei, (long long)N_EDGES + e, e64);
        int r = load_idx(et, e, t64);
        if ((unsigned)dst >= N_NODES || (unsigned)r >= N_REL) continue;
        atomicAdd(&g_scnt[dst * N_REL + r], 1);
    }
}

__global__ void k_scan1() {
    __shared__ int sdata[1024];
    int tid = threadIdx.x;
    int i = blockIdx.x * 1024 + tid;
    int v = g_scnt[i];
    g_inv[i] = (v > 0) ? (1.0f / (float)v) : 0.0f;
    sdata[tid] = v;
    __syncthreads();
    for (int off = 1; off < 1024; off <<= 1) {
        int tmp = (tid >= off) ? sdata[tid - off] : 0;
        __syncthreads();
        sdata[tid] += tmp;
        __syncthreads();
    }
    g_tmp[i] = sdata[tid];
    if (tid == 1023) g_bsum[blockIdx.x] = sdata[1023];
}

__global__ void k_scan2() {
    __shared__ int sdata[1024];
    int tid = threadIdx.x;
    int v = (tid < SCAN_BLOCKS) ? g_bsum[tid] : 0;
    sdata[tid] = v;
    __syncthreads();
    for (int off = 1; off < 1024; off <<= 1) {
        int tmp = (tid >= off) ? sdata[tid - off] : 0;
        __syncthreads();
        sdata[tid] += tmp;
        __syncthreads();
    }
    if (tid < SCAN_BLOCKS) g_bexcl[tid] = sdata[tid] - v;
}

__global__ void k_scan3() {
    int i0 = blockIdx.x * blockDim.x + threadIdx.x;
    int stride = gridDim.x * blockDim.x;
    for (int i = i0; i < NSEG; i += stride) {
        int val = g_bexcl[i >> 10] + g_tmp[i];
        g_rowptr[i + 1] = val;
        g_cursor[i] = val - g_scnt[i];
    }
    if (i0 == 0) g_rowptr[0] = 0;
}

__global__ void k_bucket(const void* __restrict__ ei, const void* __restrict__ et) {
    int i0 = blockIdx.x * blockDim.x + threadIdx.x;
    int stride = gridDim.x * blockDim.x;
    int e64 = g_ei64, t64 = g_et64;
    for (int e = i0; e < N_EDGES; e += stride) {
        int src = load_idx(ei, e, e64);
        int dst = load_idx(ei, (long long)N_EDGES + e, e64);
        int r = load_idx(et, e, t64);
        if ((unsigned)src >= N_NODES || (unsigned)dst >= N_NODES || (unsigned)r >= N_REL) continue;
        int idx = atomicAdd(&g_cursor[dst * N_REL + r], 1);
        g_esrc[idx] = (r << 16) | src;
    }
}

// ---------------- precompute: layer-2 weights to fp16, row-major [k][n] ----------
__global__ void k_wsplit(const float* __restrict__ W2, const float* __restrict__ root2) {
    int rel = blockIdx.x;
    const float* W = (rel < N_REL) ? (W2 + (size_t)rel * HID * HID) : root2;
    __half* oh = g_wt + (size_t)rel * HID * HID;
    int t = threadIdx.x;
    for (int u = t; u < 2048; u += 256) {  // 2048 units of 8 contiguous values
        int base = u * 8;
        float4 w0 = *(const float4*)&W[base];
        float4 w1 = *(const float4*)&W[base + 4];
        *(uint4*)&oh[base] = make_uint4(pack_h2(w0.x, w0.y), pack_h2(w0.z, w0.w),
                                        pack_h2(w1.x, w1.y), pack_h2(w1.z, w1.w));
    }
}

// ==================== layer 1 (fp32 SIMT, unchanged — protected win) ====================
#define L1_AS 548
#define L1_SMEM ((32 * L1_AS + 32 * 132) * 4)

__global__ void __launch_bounds__(256) k_l1(const float* __restrict__ emb,
                                            const float* __restrict__ W1,
                                            const float* __restrict__ root1,
                                            const float* __restrict__ b1) {
    extern __shared__ float sm[];
    float* As = sm;
    float* Bs = sm + 32 * L1_AS;
    int n0 = blockIdx.x * 32;
    int t = threadIdx.x;
    int d = t >> 3, sub = t & 7, f0 = sub * 2;

    float4 z4 = make_float4(0.f, 0.f, 0.f, 0.f);
#pragma unroll
    for (int q = 0; q < 16; ++q)
        *(float4*)&As[d * L1_AS + sub * 64 + q * 4] = z4;
    __syncthreads();

    int base = (n0 + d) * N_REL;
    int s = g_rowptr[base], e = g_rowptr[base + N_REL];
    for (int j = s; j < e; ++j) {
        int p = g_esrc[j];
        int src = p & 0xFFFF, rel = p >> 16;
        float2 v = *(const float2*)&emb[src * EMBD + f0];
        As[d * L1_AS + rel * 16 + f0]     += v.x;
        As[d * L1_AS + rel * 16 + f0 + 1] += v.y;
    }
#pragma unroll 8
    for (int rel = 0; rel < N_REL; ++rel) {
        float iv = g_inv[base + rel];
        As[d * L1_AS + rel * 16 + f0]     *= iv;
        As[d * L1_AS + rel * 16 + f0 + 1] *= iv;
    }
    {
        float2 rv = *(const float2*)&emb[(n0 + d) * EMBD + f0];
        As[d * L1_AS + 512 + f0]     = rv.x;
        As[d * L1_AS + 512 + f0 + 1] = rv.y;
    }

    int d0 = (t >> 5) * 4;
    int col0 = (t & 31) * 4;
    float acc[4][4];
#pragma unroll
    for (int i = 0; i < 4; i++)
#pragma unroll
        for (int j = 0; j < 4; j++) acc[i][j] = 0.f;

    for (int kc = 0; kc <= 16; ++kc) {
        int krows = (kc < 16) ? 32 : 16;
        const float* Bsrc = (kc < 16) ? (W1 + (size_t)(kc * 32) * HID) : root1;
        __syncthreads();
        {
            int row = t >> 3, c0f = (t & 7) * 16;
            if (row < krows) {
#pragma unroll
                for (int q = 0; q < 4; ++q)
                    *(float4*)&Bs[row * 132 + c0f + q * 4] =
                        *(const float4*)&Bsrc[(size_t)row * HID + c0f + q * 4];
            }
        }
        __syncthreads();
        int kbase = kc * 32;
        int nk4 = krows >> 2;
#pragma unroll 4
        for (int k4 = 0; k4 < nk4; ++k4) {
            int kb = kbase + k4 * 4;
            float4 a0 = *(const float4*)&As[(d0 + 0) * L1_AS + kb];
            float4 a1 = *(const float4*)&As[(d0 + 1) * L1_AS + kb];
            float4 a2 = *(const float4*)&As[(d0 + 2) * L1_AS + kb];
            float4 a3 = *(const float4*)&As[(d0 + 3) * L1_AS + kb];
            int kk = k4 * 4;
            float4 b0 = *(const float4*)&Bs[(kk + 0) * 132 + col0];
            float4 b1v = *(const float4*)&Bs[(kk + 1) * 132 + col0];
            float4 b2v = *(const float4*)&Bs[(kk + 2) * 132 + col0];
            float4 b3v = *(const float4*)&Bs[(kk + 3) * 132 + col0];
#define L1ROW(i, av)                                                                   \
            acc[i][0] += av.x * b0.x;  acc[i][1] += av.x * b0.y;                       \
            acc[i][2] += av.x * b0.z;  acc[i][3] += av.x * b0.w;                       \
            acc[i][0] += av.y * b1v.x; acc[i][1] += av.y * b1v.y;                      \
            acc[i][2] += av.y * b1v.z; acc[i][3] += av.y * b1v.w;                      \
            acc[i][0] += av.z * b2v.x; acc[i][1] += av.z * b2v.y;                      \
            acc[i][2] += av.z * b2v.z; acc[i][3] += av.z * b2v.w;                      \
            acc[i][0] += av.w * b3v.x; acc[i][1] += av.w * b3v.y;                      \
            acc[i][2] += av.w * b3v.z; acc[i][3] += av.w * b3v.w;
            L1ROW(0, a0) L1ROW(1, a1) L1ROW(2, a2) L1ROW(3, a3)
#undef L1ROW
        }
    }

    float4 bb = *(const float4*)&b1[col0];
#pragma unroll
    for (int i = 0; i < 4; ++i) {
        int n = n0 + d0 + i;
        float4 v = make_float4(fmaxf(acc[i][0] + bb.x, 0.f), fmaxf(acc[i][1] + bb.y, 0.f),
                               fmaxf(acc[i][2] + bb.z, 0.f), fmaxf(acc[i][3] + bb.w, 0.f));
        *(float4*)&g_h1[(size_t)n * HID + col0] = v;
    }
}

// ==================== layer 2: warp-specialized 2-pass fp16-split mma GEMM ====================
// Block = 128 dst x 128 cols, 512 threads. Warps 0-7 = consumers, 8-15 = producers.
// A split hi/lo fp16 (exact to 2^-22); B single fp16 (dropped a*b_lo term ~2^-11 rel).
// Per rel: 2 passes (ah*bh + al*bh) -> 128 mma + 64 ldsm per warp (-33% vs 3-pass bf16).
#define L2_STRIDE 136
#define L2_TILE (128 * L2_STRIDE * 2)   // 34816 bytes per fp16 tile
// smem: Abuf[b]: hi at b*2T, lo at b*2T+T (b=0,1); B at 4T
#define SM_B (4 * L2_TILE)
#define L2T_SMEM (5 * L2_TILE)          // 174080 bytes

// B copy by 256 consumer threads (ct = 0..255): single fp16 tile
__device__ __forceinline__ void l2_copy_b(char* smc, int rel, int ct) {
    const uint4* sh = (const uint4*)(g_wt + (size_t)rel * HID * HID);
#pragma unroll
    for (int i = 0; i < 8; ++i) {
        int u = ct + i * 256;           // unit of 8 fp16
        int row = u >> 4, c8 = (u & 15) * 8;
        int doff = row * L2_STRIDE + c8;
        *(uint4*)(smc + SM_B + doff * 2) = sh[u];
    }
}

// A gather by 256 producer threads: thread pt handles dst (pt>>1), cols (pt&1)*64..+63.
__device__ __forceinline__ void l2_gather(char* abase_hi, char* abase_lo, int rel,
                                          int n0, int pt) {
    __half* sA_hi = (__half*)abase_hi;
    __half* sA_lo = (__half*)abase_lo;
    int d = pt >> 1;
    int c0 = (pt & 1) * 64;
    int n = n0 + d;

    float a[64];
#pragma unroll
    for (int i = 0; i < 64; i++) a[i] = 0.f;

    if (n < N_NODES) {
        if (rel < N_REL) {
            int seg = n * N_REL + rel;
            int s = g_rowptr[seg], e = g_rowptr[seg + 1];
            for (int j = s; j < e; ++j) {
                int src = g_esrc[j] & 0xFFFF;
                const float4* hp = (const float4*)(g_h1 + (size_t)src * HID + c0);
#pragma unroll
                for (int q = 0; q < 16; ++q) {
                    float4 v = hp[q];
                    a[q * 4 + 0] += v.x;
                    a[q * 4 + 1] += v.y;
                    a[q * 4 + 2] += v.z;
                    a[q * 4 + 3] += v.w;
                }
            }
            float iv = g_inv[seg];
#pragma unroll
            for (int i = 0; i < 64; i++) a[i] *= iv;
        } else {  // root term: A = h1 row itself
            const float4* hp = (const float4*)(g_h1 + (size_t)n * HID + c0);
#pragma unroll
            for (int q = 0; q < 16; ++q) {
                float4 v = hp[q];
                a[q * 4 + 0] = v.x;
                a[q * 4 + 1] = v.y;
                a[q * 4 + 2] = v.z;
                a[q * 4 + 3] = v.w;
            }
        }
    }

    int aoff = d * L2_STRIDE + c0;
#pragma unroll
    for (int g = 0; g < 8; ++g) {   // 8 groups of 8 values
        float* ag = a + g * 8;
        float lo[8];
#pragma unroll
        for (int i = 0; i < 8; i++) {
            float h = __half2float(__float2half_rn(ag[i]));
            lo[i] = ag[i] - h;
        }
        *(uint4*)&sA_hi[aoff + g * 8] =
            make_uint4(pack_h2(ag[0], ag[1]), pack_h2(ag[2], ag[3]),
                       pack_h2(ag[4], ag[5]), pack_h2(ag[6], ag[7]));
        *(uint4*)&sA_lo[aoff + g * 8] =
            make_uint4(pack_h2(lo[0], lo[1]), pack_h2(lo[2], lo[3]),
                       pack_h2(lo[4], lo[5]), pack_h2(lo[6], lo[7]));
    }
}

__global__ void __launch_bounds__(512, 1) k_l2t(const float* __restrict__ b2,
                                                float* __restrict__ out) {
    extern __shared__ char smc[];
    uint32_t sb = smem_u32(smc);
    int t = threadIdx.x, wid = t >> 5, lane = t & 31;
    int n0 = blockIdx.x * 128;
    bool is_consumer = (wid < 8);

    if (is_consumer) {
        // ---- consumer: B copy + ldsm + mma ----
        int ct = t;                          // 0..255
        int mrow = (wid & 3) * 32, ncol = (wid >> 2) * 64;
        int l15 = lane & 15, lhi = (lane >> 4) << 3;
        int grp = lane >> 2, tg = lane & 3;

        float acc[2][8][4];
#pragma unroll
        for (int mi = 0; mi < 2; mi++)
#pragma unroll
            for (int ni = 0; ni < 8; ni++)
#pragma unroll
                for (int q = 0; q < 4; q++) acc[mi][ni][q] = 0.f;

        __syncthreads();   // producers finished gather(0) into buf 0

        for (int rel = 0; rel <= N_REL; ++rel) {
            l2_copy_b(smc, rel, ct);
            asm volatile("bar.sync 1, 256;" ::: "memory");   // consumer-only: B ready
            uint32_t ahib = sb + (rel & 1) * 2 * L2_TILE;
            uint32_t alob = ahib + L2_TILE;
            uint32_t bbase = sb + SM_B;
#pragma unroll
            for (int ks = 0; ks < 8; ++ks) {
                int k0 = ks * 16;
                uint32_t ah[2][4], al[2][4];
#pragma unroll
                for (int mi = 0; mi < 2; ++mi) {
                    uint32_t rowoff = ((mrow + mi * 16 + l15) * L2_STRIDE + k0 + lhi) * 2;
                    ldsm_x4(ah[mi][0], ah[mi][1], ah[mi][2], ah[mi][3], ahib + rowoff);
                    ldsm_x4(al[mi][0], al[mi][1], al[mi][2], al[mi][3], alob + rowoff);
                }
#pragma unroll
                for (int np = 0; np < 4; ++np) {
                    uint32_t boff = ((k0 + l15) * L2_STRIDE + ncol + np * 16 + lhi) * 2;
                    uint32_t bh0, bh1, bh2, bh3;
                    ldsm_x4_t(bh0, bh1, bh2, bh3, bbase + boff);
#pragma unroll
                    for (int mi = 0; mi < 2; ++mi) {
                        mma16816(acc[mi][np * 2 + 0], ah[mi][0], ah[mi][1], ah[mi][2], ah[mi][3], bh0, bh1);
                        mma16816(acc[mi][np * 2 + 1], ah[mi][0], ah[mi][1], ah[mi][2], ah[mi][3], bh2, bh3);
                        mma16816(acc[mi][np * 2 + 0], al[mi][0], al[mi][1], al[mi][2], al[mi][3], bh0, bh1);
                        mma16816(acc[mi][np * 2 + 1], al[mi][0], al[mi][1], al[mi][2], al[mi][3], bh2, bh3);
                    }
                }
            }
            __syncthreads();   // mma(rel) done everywhere; gather(rel+1) complete
        }

        // ---- epilogue: + b2 -> out ----
#pragma unroll
        for (int mi = 0; mi < 2; ++mi) {
            int r0 = n0 + mrow + mi * 16 + grp;
#pragma unroll
            for (int ni = 0; ni < 8; ++ni) {
                int col = ncol + ni * 8 + tg * 2;
                float2 bb = *(const float2*)&b2[col];
                if (r0 < N_NODES)
                    *(float2*)&out[(size_t)r0 * HID + col] =
                        make_float2(acc[mi][ni][0] + bb.x, acc[mi][ni][1] + bb.y);
                if (r0 + 8 < N_NODES)
                    *(float2*)&out[(size_t)(r0 + 8) * HID + col] =
                        make_float2(acc[mi][ni][2] + bb.x, acc[mi][ni][3] + bb.y);
            }
        }
    } else {
        // ---- producer: gather A(rel+1) while consumers mma(rel) ----
        int pt = t - 256;                    // 0..255

        // prologue: gather(0) into buffer 0
        l2_gather(smc + 0, smc + L2_TILE, 0, n0, pt);
        __syncthreads();

        for (int rel = 0; rel <= N_REL; ++rel) {
            if (rel < N_REL) {
                int nb = (rel + 1) & 1;
                l2_gather(smc + nb * 2 * L2_TILE, smc + nb * 2 * L2_TILE + L2_TILE,
                          rel + 1, n0, pt);
            }
            __syncthreads();
        }
    }
}

// ---------------- launch ----------------
extern "C" void kernel_launch(void* const* d_in, const int* in_sizes, int n_in,
                              void* d_out, int out_size) {
    const void* edge_index = d_in[0];
    const void* edge_type = d_in[1];
    const float* node_emb = (const float*)d_in[2];
    const float* W1 = (const float*)d_in[3];
    const float* root1 = (const float*)d_in[4];
    const float* b1 = (const float*)d_in[5];
    const float* W2 = (const float*)d_in[6];
    const float* root2 = (const float*)d_in[7];
    const float* b2 = (const float*)d_in[8];
    float* out = (float*)d_out;

    static int attr_done = 0;
    if (!attr_done) {
        cudaFuncSetAttribute(k_l1, cudaFuncAttributeMaxDynamicSharedMemorySize, L1_SMEM);
        cudaFuncSetAttribute(k_l2t, cudaFuncAttributeMaxDynamicSharedMemorySize, L2T_SMEM);
        attr_done = 1;
    }

    k_detect<<<1, 32>>>((const int*)edge_index, (const int*)edge_type);

    k_init<<<640, 1024>>>();
    k_count<<<1172, 256>>>(edge_index, edge_type);
    k_scan1<<<SCAN_BLOCKS, 1024>>>();
    k_scan2<<<1, 1024>>>();
    k_scan3<<<640, 1024>>>();
    k_bucket<<<1172, 256>>>(edge_index, edge_type);
    k_wsplit<<<33, 256>>>(W2, root2);

    k_l1<<<625, 256, L1_SMEM>>>(node_emb, W1, root1, b1);
    k_l2t<<<157, 512, L2T_SMEM>>>(b2, out);   // 512 threads: 8 consumer + 8 producer warps
}

// round 17
// speedup vs baseline: 3.4509x; 1.1144x over previous
#include <cuda_runtime.h>
#include <cuda_bf16.h>
#include <cuda_fp16.h>
#include <cstdint>

#define N_NODES 20000
#define N_REL 32
#define HID 128
#define EMBD 16
#define N_EDGES 600000
#define NSEG (N_NODES * N_REL)    // 640000
#define SCAN_BLOCKS (NSEG / 1024) // 625 exactly

// ---------------- scratch (device globals, 16B-aligned; ~26 MB) ----------------
__device__ __align__(16) int   g_scnt[NSEG];
__device__ __align__(16) int   g_tmp[NSEG];
__device__ __align__(16) int   g_rowptr[NSEG + 1];
__device__ __align__(16) int   g_cursor[NSEG];
__device__ __align__(16) float g_inv[NSEG];
__device__ __align__(16) int   g_esrc[N_EDGES];     // (rel<<16)|src per edge, bucketed by segment
__device__ __align__(16) float g_h1[N_NODES * HID];
__device__ __align__(16) int   g_bsum[SCAN_BLOCKS];
__device__ __align__(16) int   g_bexcl[SCAN_BLOCKS];
// fp16 layer-2 weights, natural row-major [k][n]: 33 rels x [128][128]
__device__ __align__(16) __half g_wt[33 * 128 * 128];
__device__ int g_ei64;
__device__ int g_et64;

__device__ __forceinline__ int load_idx(const void* p, long long i, int is64) {
    return is64 ? (int)((const long long*)p)[i] : ((const int*)p)[i];
}

__device__ __forceinline__ uint32_t smem_u32(const void* p) {
    uint32_t a;
    asm("{ .reg .u64 t; cvta.to.shared.u64 t, %1; cvt.u32.u64 %0, t; }" : "=r"(a) : "l"(p));
    return a;
}

__device__ __forceinline__ uint32_t pack_h2(float x, float y) {
    __half2 h = __floats2half2_rn(x, y);
    return *(uint32_t*)&h;
}

__device__ __forceinline__ void ldsm_x4(uint32_t& r0, uint32_t& r1, uint32_t& r2, uint32_t& r3,
                                        uint32_t addr) {
    asm volatile("ldmatrix.sync.aligned.m8n8.x4.shared.b16 {%0,%1,%2,%3}, [%4];"
                 : "=r"(r0), "=r"(r1), "=r"(r2), "=r"(r3) : "r"(addr));
}
__device__ __forceinline__ void ldsm_x4_t(uint32_t& r0, uint32_t& r1, uint32_t& r2, uint32_t& r3,
                                          uint32_t addr) {
    asm volatile("ldmatrix.sync.aligned.m8n8.x4.trans.shared.b16 {%0,%1,%2,%3}, [%4];"
                 : "=r"(r0), "=r"(r1), "=r"(r2), "=r"(r3) : "r"(addr));
}
__device__ __forceinline__ void mma16816(float* c, uint32_t a0, uint32_t a1, uint32_t a2,
                                         uint32_t a3, uint32_t b0, uint32_t b1) {
    asm volatile(
        "mma.sync.aligned.m16n8k16.row.col.f32.f16.f16.f32 "
        "{%0,%1,%2,%3}, {%4,%5,%6,%7}, {%8,%9}, {%0,%1,%2,%3};"
        : "+f"(c[0]), "+f"(c[1]), "+f"(c[2]), "+f"(c[3])
        : "r"(a0), "r"(a1), "r"(a2), "r"(a3), "r"(b0), "r"(b1));
}

// ---------------- dtype detection (int32 vs int64 index arrays) ----------------
__global__ void k_detect(const int* __restrict__ ei, const int* __restrict__ et) {
    if (blockIdx.x == 0 && threadIdx.x == 0) {
        int a = 1, b = 1;
        for (int i = 0; i < 64; i++) if (ei[2 * i + 1] != 0) { a = 0; break; }
        for (int i = 0; i < 64; i++) if (et[2 * i + 1] != 0) { b = 0; break; }
        g_ei64 = a;
        g_et64 = b;
    }
}

// ---------------- preprocessing ----------------
__global__ void k_init() {
    int i0 = blockIdx.x * blockDim.x + threadIdx.x;
    int stride = gridDim.x * blockDim.x;
    for (int i = i0; i < NSEG; i += stride) g_scnt[i] = 0;
}

__global__ void k_count(const void* __restrict__ ei, const void* __restrict__ et) {
    int i0 = blockIdx.x * blockDim.x + threadIdx.x;
    int stride = gridDim.x * blockDim.x;
    int e64 = g_ei64, t64 = g_et64;
    for (int e = i0; e < N_EDGES; e += stride) {
        int dst = load_idx(ei, (long long)N_EDGES + e, e64);
        int r = load_idx(et, e, t64);
        if ((unsigned)dst >= N_NODES || (unsigned)r >= N_REL) continue;
        atomicAdd(&g_scnt[dst * N_REL + r], 1);
    }
}

__global__ void k_scan1() {
    __shared__ int sdata[1024];
    int tid = threadIdx.x;
    int i = blockIdx.x * 1024 + tid;
    int v = g_scnt[i];
    g_inv[i] = (v > 0) ? (1.0f / (float)v) : 0.0f;
    sdata[tid] = v;
    __syncthreads();
    for (int off = 1; off < 1024; off <<= 1) {
        int tmp = (tid >= off) ? sdata[tid - off] : 0;
        __syncthreads();
        sdata[tid] += tmp;
        __syncthreads();
    }
    g_tmp[i] = sdata[tid];
    if (tid == 1023) g_bsum[blockIdx.x] = sdata[1023];
}

__global__ void k_scan2() {
    __shared__ int sdata[1024];
    int tid = threadIdx.x;
    int v = (tid < SCAN_BLOCKS) ? g_bsum[tid] : 0;
    sdata[tid] = v;
    __syncthreads();
    for (int off = 1; off < 1024; off <<= 1) {
        int tmp = (tid >= off) ? sdata[tid - off] : 0;
        __syncthreads();
        sdata[tid] += tmp;
        __syncthreads();
    }
    if (tid < SCAN_BLOCKS) g_bexcl[tid] = sdata[tid] - v;
}

__global__ void k_scan3() {
    int i0 = blockIdx.x * blockDim.x + threadIdx.x;
    int stride = gridDim.x * blockDim.x;
    for (int i = i0; i < NSEG; i += stride) {
        int val = g_bexcl[i >> 10] + g_tmp[i];
        g_rowptr[i + 1] = val;
        g_cursor[i] = val - g_scnt[i];
    }
    if (i0 == 0) g_rowptr[0] = 0;
}

__global__ void k_bucket(const void* __restrict__ ei, const void* __restrict__ et) {
    int i0 = blockIdx.x * blockDim.x + threadIdx.x;
    int stride = gridDim.x * blockDim.x;
    int e64 = g_ei64, t64 = g_et64;
    for (int e = i0; e < N_EDGES; e += stride) {
        int src = load_idx(ei, e, e64);
        int dst = load_idx(ei, (long long)N_EDGES + e, e64);
        int r = load_idx(et, e, t64);
        if ((unsigned)src >= N_NODES || (unsigned)dst >= N_NODES || (unsigned)r >= N_REL) continue;
        int idx = atomicAdd(&g_cursor[dst * N_REL + r], 1);
        g_esrc[idx] = (r << 16) | src;
    }
}

// ---------------- precompute: layer-2 weights to fp16, row-major [k][n] ----------
__global__ void k_wsplit(const float* __restrict__ W2, const float* __restrict__ root2) {
    int rel = blockIdx.x;
    const float* W = (rel < N_REL) ? (W2 + (size_t)rel * HID * HID) : root2;
    __half* oh = g_wt + (size_t)rel * HID * HID;
    int t = threadIdx.x;
    for (int u = t; u < 2048; u += 256) {  // 2048 units of 8 contiguous values
        int base = u * 8;
        float4 w0 = *(const float4*)&W[base];
        float4 w1 = *(const float4*)&W[base + 4];
        *(uint4*)&oh[base] = make_uint4(pack_h2(w0.x, w0.y), pack_h2(w0.z, w0.w),
                                        pack_h2(w1.x, w1.y), pack_h2(w1.z, w1.w));
    }
}

// ==================== layer 1 (fp32 SIMT, unchanged — protected win) ====================
#define L1_AS 548
#define L1_SMEM ((32 * L1_AS + 32 * 132) * 4)

__global__ void __launch_bounds__(256) k_l1(const float* __restrict__ emb,
                                            const float* __restrict__ W1,
                                            const float* __restrict__ root1,
                                            const float* __restrict__ b1) {
    extern __shared__ float sm[];
    float* As = sm;
    float* Bs = sm + 32 * L1_AS;
    int n0 = blockIdx.x * 32;
    int t = threadIdx.x;
    int d = t >> 3, sub = t & 7, f0 = sub * 2;

    float4 z4 = make_float4(0.f, 0.f, 0.f, 0.f);
#pragma unroll
    for (int q = 0; q < 16; ++q)
        *(float4*)&As[d * L1_AS + sub * 64 + q * 4] = z4;
    __syncthreads();

    int base = (n0 + d) * N_REL;
    int s = g_rowptr[base], e = g_rowptr[base + N_REL];
    for (int j = s; j < e; ++j) {
        int p = g_esrc[j];
        int src = p & 0xFFFF, rel = p >> 16;
        float2 v = *(const float2*)&emb[src * EMBD + f0];
        As[d * L1_AS + rel * 16 + f0]     += v.x;
        As[d * L1_AS + rel * 16 + f0 + 1] += v.y;
    }
#pragma unroll 8
    for (int rel = 0; rel < N_REL; ++rel) {
        float iv = g_inv[base + rel];
        As[d * L1_AS + rel * 16 + f0]     *= iv;
        As[d * L1_AS + rel * 16 + f0 + 1] *= iv;
    }
    {
        float2 rv = *(const float2*)&emb[(n0 + d) * EMBD + f0];
        As[d * L1_AS + 512 + f0]     = rv.x;
        As[d * L1_AS + 512 + f0 + 1] = rv.y;
    }

    int d0 = (t >> 5) * 4;
    int col0 = (t & 31) * 4;
    float acc[4][4];
#pragma unroll
    for (int i = 0; i < 4; i++)
#pragma unroll
        for (int j = 0; j < 4; j++) acc[i][j] = 0.f;

    for (int kc = 0; kc <= 16; ++kc) {
        int krows = (kc < 16) ? 32 : 16;
        const float* Bsrc = (kc < 16) ? (W1 + (size_t)(kc * 32) * HID) : root1;
        __syncthreads();
        {
            int row = t >> 3, c0f = (t & 7) * 16;
            if (row < krows) {
#pragma unroll
                for (int q = 0; q < 4; ++q)
                    *(float4*)&Bs[row * 132 + c0f + q * 4] =
                        *(const float4*)&Bsrc[(size_t)row * HID + c0f + q * 4];
            }
        }
        __syncthreads();
        int kbase = kc * 32;
        int nk4 = krows >> 2;
#pragma unroll 4
        for (int k4 = 0; k4 < nk4; ++k4) {
            int kb = kbase + k4 * 4;
            float4 a0 = *(const float4*)&As[(d0 + 0) * L1_AS + kb];
            float4 a1 = *(const float4*)&As[(d0 + 1) * L1_AS + kb];
            float4 a2 = *(const float4*)&As[(d0 + 2) * L1_AS + kb];
            float4 a3 = *(const float4*)&As[(d0 + 3) * L1_AS + kb];
            int kk = k4 * 4;
            float4 b0 = *(const float4*)&Bs[(kk + 0) * 132 + col0];
            float4 b1v = *(const float4*)&Bs[(kk + 1) * 132 + col0];
            float4 b2v = *(const float4*)&Bs[(kk + 2) * 132 + col0];
            float4 b3v = *(const float4*)&Bs[(kk + 3) * 132 + col0];
#define L1ROW(i, av)                                                                   \
            acc[i][0] += av.x * b0.x;  acc[i][1] += av.x * b0.y;                       \
            acc[i][2] += av.x * b0.z;  acc[i][3] += av.x * b0.w;                       \
            acc[i][0] += av.y * b1v.x; acc[i][1] += av.y * b1v.y;                      \
            acc[i][2] += av.y * b1v.z; acc[i][3] += av.y * b1v.w;                      \
            acc[i][0] += av.z * b2v.x; acc[i][1] += av.z * b2v.y;                      \
            acc[i][2] += av.z * b2v.z; acc[i][3] += av.z * b2v.w;                      \
            acc[i][0] += av.w * b3v.x; acc[i][1] += av.w * b3v.y;                      \
            acc[i][2] += av.w * b3v.z; acc[i][3] += av.w * b3v.w;
            L1ROW(0, a0) L1ROW(1, a1) L1ROW(2, a2) L1ROW(3, a3)
#undef L1ROW
        }
    }

    float4 bb = *(const float4*)&b1[col0];
#pragma unroll
    for (int i = 0; i < 4; ++i) {
        int n = n0 + d0 + i;
        float4 v = make_float4(fmaxf(acc[i][0] + bb.x, 0.f), fmaxf(acc[i][1] + bb.y, 0.f),
                               fmaxf(acc[i][2] + bb.z, 0.f), fmaxf(acc[i][3] + bb.w, 0.f));
        *(float4*)&g_h1[(size_t)n * HID + col0] = v;
    }
}

// ==================== layer 2: warp-specialized single-pass fp16 mma GEMM ====================
// Block = 128 dst x 128 cols, 512 threads. Warps 0-7 = consumers, 8-15 = producers.
// A single fp16, B single fp16 (quantization err ~2e-4 each, quadrature ~3e-4 total).
// Per rel: 64 mma + 48 ldsm per consumer warp.
#define L2_STRIDE 136
#define L2_TILE (128 * L2_STRIDE * 2)   // 34816 bytes per fp16 tile
// smem: Abuf[b] at b*T (b=0,1); B at 2T
#define SM_B (2 * L2_TILE)
#define L2T_SMEM (3 * L2_TILE)          // 104448 bytes

// B copy by 256 consumer threads (ct = 0..255): single fp16 tile
__device__ __forceinline__ void l2_copy_b(char* smc, int rel, int ct) {
    const uint4* sh = (const uint4*)(g_wt + (size_t)rel * HID * HID);
#pragma unroll
    for (int i = 0; i < 8; ++i) {
        int u = ct + i * 256;           // unit of 8 fp16
        int row = u >> 4, c8 = (u & 15) * 8;
        int doff = row * L2_STRIDE + c8;
        *(uint4*)(smc + SM_B + doff * 2) = sh[u];
    }
}

// A gather by 256 producer threads: thread pt handles dst (pt>>1), cols (pt&1)*64..+63.
__device__ __forceinline__ void l2_gather(char* abase, int rel, int n0, int pt) {
    __half* sA = (__half*)abase;
    int d = pt >> 1;
    int c0 = (pt & 1) * 64;
    int n = n0 + d;

    float a[64];
#pragma unroll
    for (int i = 0; i < 64; i++) a[i] = 0.f;

    if (n < N_NODES) {
        if (rel < N_REL) {
            int seg = n * N_REL + rel;
            int s = g_rowptr[seg], e = g_rowptr[seg + 1];
            for (int j = s; j < e; ++j) {
                int src = g_esrc[j] & 0xFFFF;
                const float4* hp = (const float4*)(g_h1 + (size_t)src * HID + c0);
#pragma unroll
                for (int q = 0; q < 16; ++q) {
                    float4 v = hp[q];
                    a[q * 4 + 0] += v.x;
                    a[q * 4 + 1] += v.y;
                    a[q * 4 + 2] += v.z;
                    a[q * 4 + 3] += v.w;
                }
            }
            float iv = g_inv[seg];
#pragma unroll
            for (int i = 0; i < 64; i++) a[i] *= iv;
        } else {  // root term: A = h1 row itself
            const float4* hp = (const float4*)(g_h1 + (size_t)n * HID + c0);
#pragma unroll
            for (int q = 0; q < 16; ++q) {
                float4 v = hp[q];
                a[q * 4 + 0] = v.x;
                a[q * 4 + 1] = v.y;
                a[q * 4 + 2] = v.z;
                a[q * 4 + 3] = v.w;
            }
        }
    }

    int aoff = d * L2_STRIDE + c0;
#pragma unroll
    for (int g = 0; g < 8; ++g) {   // 8 groups of 8 values
        float* ag = a + g * 8;
        *(uint4*)&sA[aoff + g * 8] =
            make_uint4(pack_h2(ag[0], ag[1]), pack_h2(ag[2], ag[3]),
                       pack_h2(ag[4], ag[5]), pack_h2(ag[6], ag[7]));
    }
}

__global__ void __launch_bounds__(512, 1) k_l2t(const float* __restrict__ b2,
                                                float* __restrict__ out) {
    extern __shared__ char smc[];
    uint32_t sb = smem_u32(smc);
    int t = threadIdx.x, wid = t >> 5, lane = t & 31;
    int n0 = blockIdx.x * 128;
    bool is_consumer = (wid < 8);

    if (is_consumer) {
        // ---- consumer: B copy + ldsm + mma ----
        int ct = t;                          // 0..255
        int mrow = (wid & 3) * 32, ncol = (wid >> 2) * 64;
        int l15 = lane & 15, lhi = (lane >> 4) << 3;
        int grp = lane >> 2, tg = lane & 3;

        float acc[2][8][4];
#pragma unroll
        for (int mi = 0; mi < 2; mi++)
#pragma unroll
            for (int ni = 0; ni < 8; ni++)
#pragma unroll
                for (int q = 0; q < 4; q++) acc[mi][ni][q] = 0.f;

        __syncthreads();   // producers finished gather(0) into buf 0

        for (int rel = 0; rel <= N_REL; ++rel) {
            l2_copy_b(smc, rel, ct);
            asm volatile("bar.sync 1, 256;" ::: "memory");   // consumer-only: B ready
            uint32_t abase = sb + (rel & 1) * L2_TILE;
            uint32_t bbase = sb + SM_B;
#pragma unroll
            for (int ks = 0; ks < 8; ++ks) {
                int k0 = ks * 16;
                uint32_t ah[2][4];
#pragma unroll
                for (int mi = 0; mi < 2; ++mi) {
                    uint32_t rowoff = ((mrow + mi * 16 + l15) * L2_STRIDE + k0 + lhi) * 2;
                    ldsm_x4(ah[mi][0], ah[mi][1], ah[mi][2], ah[mi][3], abase + rowoff);
                }
#pragma unroll
                for (int np = 0; np < 4; ++np) {
                    uint32_t boff = ((k0 + l15) * L2_STRIDE + ncol + np * 16 + lhi) * 2;
                    uint32_t bh0, bh1, bh2, bh3;
                    ldsm_x4_t(bh0, bh1, bh2, bh3, bbase + boff);
#pragma unroll
                    for (int mi = 0; mi < 2; ++mi) {
                        mma16816(acc[mi][np * 2 + 0], ah[mi][0], ah[mi][1], ah[mi][2], ah[mi][3], bh0, bh1);
                        mma16816(acc[mi][np * 2 + 1], ah[mi][0], ah[mi][1], ah[mi][2], ah[mi][3], bh2, bh3);
                    }
                }
            }
            __syncthreads();   // mma(rel) done everywhere; gather(rel+1) complete
        }

        // ---- epilogue: + b2 -> out ----
#pragma unroll
        for (int mi = 0; mi < 2; ++mi) {
            int r0 = n0 + mrow + mi * 16 + grp;
#pragma unroll
            for (int ni = 0; ni < 8; ++ni) {
                int col = ncol + ni * 8 + tg * 2;
                float2 bb = *(const float2*)&b2[col];
                if (r0 < N_NODES)
                    *(float2*)&out[(size_t)r0 * HID + col] =
                        make_float2(acc[mi][ni][0] + bb.x, acc[mi][ni][1] + bb.y);
                if (r0 + 8 < N_NODES)
                    *(float2*)&out[(size_t)(r0 + 8) * HID + col] =
                        make_float2(acc[mi][ni][2] + bb.x, acc[mi][ni][3] + bb.y);
            }
        }
    } else {
        // ---- producer: gather A(rel+1) while consumers mma(rel) ----
        int pt = t - 256;                    // 0..255

        // prologue: gather(0) into buffer 0
        l2_gather(smc + 0, 0, n0, pt);
        __syncthreads();

        for (int rel = 0; rel <= N_REL; ++rel) {
            if (rel < N_REL) {
                int nb = (rel + 1) & 1;
                l2_gather(smc + nb * L2_TILE, rel + 1, n0, pt);
            }
            __syncthreads();
        }
    }
}

// ---------------- launch ----------------
extern "C" void kernel_launch(void* const* d_in, const int* in_sizes, int n_in,
                              void* d_out, int out_size) {
    const void* edge_index = d_in[0];
    const void* edge_type = d_in[1];
    const float* node_emb = (const float*)d_in[2];
    const float* W1 = (const float*)d_in[3];
    const float* root1 = (const float*)d_in[4];
    const float* b1 = (const float*)d_in[5];
    const float* W2 = (const float*)d_in[6];
    const float* root2 = (const float*)d_in[7];
    const float* b2 = (const float*)d_in[8];
    float* out = (float*)d_out;

    static int attr_done = 0;
    if (!attr_done) {
        cudaFuncSetAttribute(k_l1, cudaFuncAttributeMaxDynamicSharedMemorySize, L1_SMEM);
        cudaFuncSetAttribute(k_l2t, cudaFuncAttributeMaxDynamicSharedMemorySize, L2T_SMEM);
        attr_done = 1;
    }

    k_detect<<<1, 32>>>((const int*)edge_index, (const int*)edge_type);

    k_init<<<640, 1024>>>();
    k_count<<<1172, 256>>>(edge_index, edge_type);
    k_scan1<<<SCAN_BLOCKS, 1024>>>();
    k_scan2<<<1, 1024>>>();
    k_scan3<<<640, 1024>>>();
    k_bucket<<<1172, 256>>>(edge_index, edge_type);
    k_wsplit<<<33, 256>>>(W2, root2);

    k_l1<<<625, 256, L1_SMEM>>>(node_emb, W1, root1, b1);
    k_l2t<<<157, 512, L2T_SMEM>>>(b2, out);   // 512 threads: 8 consumer + 8 producer warps
}